// round 9
// baseline (speedup 1.0000x reference)
#include <cuda_runtime.h>
#include <cuda_fp16.h>
#include <math.h>
#include <stdint.h>

// Problem dims
#define SEQ   128
#define BATCH 256
#define IND   1024
#define HID   1024
#define OUTD  1024
#define G4    4096
#define BH    (BATCH*HID)
#define KA    1024            // activations: fp16, rounded once
#define KB    2048            // recurrence weights: [hi | lo] fp16 split
#define BK    32

// ---------------- scratch (device globals) ---------------------------------
__device__ float g_Xp[(size_t)SEQ * BATCH * G4];     // 512 MB (gate-interleaved cols)
__device__ float g_hs[(size_t)SEQ * BATCH * HID];    // 128 MB
__device__ float g_A[SEQ * SEQ];
__device__ float g_bias[G4];                          // gate-interleaved
__device__ __half g_Xbf[(size_t)SEQ * BATCH * KA];    // 64 MB: X16 then att16
__device__ __half g_Wihp[(size_t)G4 * KA];            // 8 MB (single fp16, gate-perm)
__device__ __half g_Whhp[(size_t)G4 * KB];            // 16 MB (2-term split, gate-perm)
__device__ __half g_linWp[(size_t)OUTD * KA];         // 2 MB (single fp16)
__device__ __half g_hp[(size_t)2 * BATCH * KA];       // double-buffered h16
__device__ unsigned g_bar_cnt;
__device__ unsigned g_bar_gen;

// ---------------- PTX helpers ----------------------------------------------
__device__ __forceinline__ uint32_t smem_u32(const void* p) {
    uint32_t a;
    asm("{ .reg .u64 t; cvta.to.shared.u64 t, %1; cvt.u32.u64 %0, t; }"
        : "=r"(a) : "l"(p));
    return a;
}

#define CP_ASYNC16(dst, src) \
    asm volatile("cp.async.cg.shared.global [%0], [%1], 16;" :: "r"(dst), "l"(src))
#define CP_COMMIT()  asm volatile("cp.async.commit_group;" ::: "memory")
#define CP_WAIT2()   asm volatile("cp.async.wait_group 2;" ::: "memory")
#define CP_WAIT1()   asm volatile("cp.async.wait_group 1;" ::: "memory")
#define CP_WAIT0()   asm volatile("cp.async.wait_group 0;" ::: "memory")

#define LDMX4(r0, r1, r2, r3, addr) \
    asm volatile("ldmatrix.sync.aligned.m8n8.x4.shared.b16 {%0,%1,%2,%3}, [%4];" \
                 : "=r"(r0), "=r"(r1), "=r"(r2), "=r"(r3) : "r"(addr))

#define MMA16816(d, a, b) \
    asm volatile("mma.sync.aligned.m16n8k16.row.col.f32.f16.f16.f32 " \
                 "{%0,%1,%2,%3}, {%4,%5,%6,%7}, {%8,%9}, {%0,%1,%2,%3};" \
                 : "+f"((d)[0]), "+f"((d)[1]), "+f"((d)[2]), "+f"((d)[3]) \
                 : "r"((a)[0]), "r"((a)[1]), "r"((a)[2]), "r"((a)[3]), \
                   "r"((b)[0]), "r"((b)[1]))

// swizzled 16B-chunk byte offset within a tile (row has 4 chunks of 8 fp16)
__device__ __forceinline__ uint32_t swz(int row, int c) {
    return (uint32_t)((row * 4 + (c ^ ((row >> 1) & 3))) * 16);
}

__device__ __forceinline__ float sigmf(float x) {
    return 1.0f / (1.0f + __expf(-x));
}

__device__ __forceinline__ unsigned ld_acq(unsigned* p) {
    unsigned v;
    asm volatile("ld.acquire.gpu.global.u32 %0, [%1];" : "=r"(v) : "l"(p) : "memory");
    return v;
}

// ---------------- fp16 HMMA GEMM (big one-shot GEMMs) -----------------------
// C[M,N] = A16[M,KA] @ B16[N,KBB]^T (+bias), fp32 accum; A chunk index wraps
// mod KA (for KBB>KA the B blocks beyond KA are lo-terms of a split).
// 256 threads = 8 warps (WGM x WGN). BK=32, 4-stage cp.async, 1 sync/chunk.
template<int BM, int BN, int WGM, int WGN, int KBB>
__global__ __launch_bounds__(256)
void gemm_mma(const __half* __restrict__ A,
              const __half* __restrict__ B,
              const float* __restrict__ bias,
              float* __restrict__ C,
              int N, int hasBias)
{
    constexpr int NCC = KBB / BK;
    constexpr int WM = BM / WGM;
    constexpr int WN = BN / WGN;
    constexpr int MA = WM / 16;
    constexpr int NA = WN / 8;
    constexpr int A_BYTES = BM * BK * 2;
    constexpr int B_BYTES = BN * BK * 2;
    constexpr int STAGE   = A_BYTES + B_BYTES;

    extern __shared__ __align__(128) char smem[];
    const uint32_t sb = smem_u32(smem);

    const int tid = threadIdx.x;
    const int wid = tid >> 5;
    const int lid = tid & 31;
    const int g   = lid >> 2;
    const int tg  = lid & 3;
    const int wm  = wid / WGN;
    const int wn  = wid % WGN;
    const int bm0 = blockIdx.y * BM;
    const int bn0 = blockIdx.x * BN;

    float acc[MA][NA][4];
    #pragma unroll
    for (int i = 0; i < MA; ++i)
        #pragma unroll
        for (int j = 0; j < NA; ++j)
            #pragma unroll
            for (int q = 0; q < 4; ++q) acc[i][j][q] = 0.f;

    auto load_tile = [&](int c, int s) {
        const uint32_t abase = sb + s * STAGE;
        const uint32_t bbase = abase + A_BYTES;
        const int ka0 = (c & (KA / BK - 1)) * BK;   // A wraps
        const int kb0 = c * BK;
        #pragma unroll
        for (int u = tid; u < BM * 4; u += 256) {
            int r = u >> 2, cc = u & 3;
            CP_ASYNC16(abase + swz(r, cc),
                       A + (size_t)(bm0 + r) * KA + ka0 + cc * 8);
        }
        #pragma unroll
        for (int u = tid; u < BN * 4; u += 256) {
            int r = u >> 2, cc = u & 3;
            CP_ASYNC16(bbase + swz(r, cc),
                       B + (size_t)(bn0 + r) * KBB + kb0 + cc * 8);
        }
    };

    load_tile(0, 0); CP_COMMIT();
    load_tile(1, 1); CP_COMMIT();
    load_tile(2, 2); CP_COMMIT();

    for (int c = 0; c < NCC; ++c) {
        if (c <= NCC - 3)      { CP_WAIT2(); }
        else if (c == NCC - 2) { CP_WAIT1(); }
        else                   { CP_WAIT0(); }
        __syncthreads();
        if (c + 3 < NCC) { load_tile(c + 3, (c + 3) & 3); CP_COMMIT(); }

        const uint32_t abase = sb + (c & 3) * STAGE;
        const uint32_t bbase = abase + A_BYTES;

        #pragma unroll
        for (int ks = 0; ks < 2; ++ks) {
            uint32_t afr[MA][4];
            #pragma unroll
            for (int ma = 0; ma < MA; ++ma) {
                int row = wm * WM + ma * 16 + (lid & 15);
                int cc  = 2 * ks + (lid >> 4);
                LDMX4(afr[ma][0], afr[ma][1], afr[ma][2], afr[ma][3],
                      abase + swz(row, cc));
            }
            uint32_t bfr[NA][2];
            #pragma unroll
            for (int np = 0; np < NA / 2; ++np) {
                int row = wn * WN + np * 16 + (lid & 15);
                int cc  = 2 * ks + (lid >> 4);
                uint32_t r0, r1, r2, r3;
                LDMX4(r0, r1, r2, r3, bbase + swz(row, cc));
                bfr[2 * np + 0][0] = r0; bfr[2 * np + 1][0] = r1;
                bfr[2 * np + 0][1] = r2; bfr[2 * np + 1][1] = r3;
            }
            #pragma unroll
            for (int ma = 0; ma < MA; ++ma)
                #pragma unroll
                for (int na = 0; na < NA; ++na)
                    MMA16816(acc[ma][na], afr[ma], bfr[na]);
        }
    }

    #pragma unroll
    for (int ma = 0; ma < MA; ++ma) {
        #pragma unroll
        for (int na = 0; na < NA; ++na) {
            const int col = bn0 + wn * WN + na * 8 + tg * 2;
            const int r0  = bm0 + wm * WM + ma * 16 + g;
            const int r1  = r0 + 8;
            float2 v0 = make_float2(acc[ma][na][0], acc[ma][na][1]);
            float2 v1 = make_float2(acc[ma][na][2], acc[ma][na][3]);
            if (hasBias) {
                float2 bv = *reinterpret_cast<const float2*>(bias + col);
                v0.x += bv.x; v0.y += bv.y; v1.x += bv.x; v1.y += bv.y;
            }
            *reinterpret_cast<float2*>(C + (size_t)r0 * N + col) = v0;
            *reinterpret_cast<float2*>(C + (size_t)r1 * N + col) = v1;
        }
    }
}

// ---------------- persistent LSTM recurrence --------------------------------
// 128 CTAs (grid 32x4), all resident. Per step: 64x128 tile of
// gates = h16 @ W_hh'^T (KB=2048, A wraps mod 1024), Xp[t] tile prefetched,
// fused pointwise with c-state in registers, then software grid barrier.
__global__ __launch_bounds__(256)
void lstm_persistent(const __half* __restrict__ Whhp,
                     const float* __restrict__ Xp,
                     const float* __restrict__ c0,
                     float* __restrict__ hs,
                     __half* __restrict__ hp)
{
    constexpr int NC = KB / BK;                 // 64
    constexpr int BM = 64, BN = 128, WGN = 4;
    constexpr int WM = 32, WN = 32, MA = 2, NA = 4;
    constexpr int A_BYTES = BM * BK * 2;        // 4096
    constexpr int B_BYTES = BN * BK * 2;        // 8192
    constexpr int STG     = A_BYTES + B_BYTES;  // 12288
    constexpr int XP_OFF  = 4 * STG;            // 49152 (also > st region 33792)
    constexpr int BNP     = BN + 4;

    extern __shared__ __align__(128) char smem[];
    const uint32_t sb = smem_u32(smem);
    float* st   = reinterpret_cast<float*>(smem);            // [0, 33792)
    float* xp_s = reinterpret_cast<float*>(smem + XP_OFF);   // [49152, 81920)

    const int tid = threadIdx.x;
    const int wid = tid >> 5;
    const int lid = tid & 31;
    const int wm  = wid / WGN;
    const int wn  = wid % WGN;
    const int bn0 = blockIdx.x * BN;
    const int bm0 = blockIdx.y * BM;
    const int j0  = bn0 >> 2;

    float c_reg[8];
    #pragma unroll
    for (int k = 0; k < 8; ++k) {
        int idx = tid + 256 * k;
        int r = idx >> 5, jj = idx & 31;
        c_reg[k] = c0[(bm0 + r) * HID + j0 + jj];
    }

    unsigned bar_base = 0;
    if (tid == 0) bar_base = ld_acq(&g_bar_gen);

    for (int t = 0; t < SEQ; ++t) {
        const __half* Ap = hp + (size_t)(t & 1) * BATCH * KA;
        __half* hpn = hp + (size_t)((t + 1) & 1) * BATCH * KA;

        float acc[MA][NA][4];
        #pragma unroll
        for (int i = 0; i < MA; ++i)
            #pragma unroll
            for (int j = 0; j < NA; ++j)
                #pragma unroll
                for (int q = 0; q < 4; ++q) acc[i][j][q] = 0.f;

        auto load_chunk = [&](int c, int s) {
            const uint32_t ab = sb + s * STG;
            const uint32_t bb = ab + A_BYTES;
            const int ka0 = (c & (KA / BK - 1)) * BK;
            const int kb0 = c * BK;
            {   // A: 64 rows x 4 chunks = 256, one per thread
                int r = tid >> 2, cc = tid & 3;
                CP_ASYNC16(ab + swz(r, cc),
                           Ap + (size_t)(bm0 + r) * KA + ka0 + cc * 8);
            }
            #pragma unroll
            for (int it = 0; it < 2; ++it) {
                int u = tid + it * 256;
                int r = u >> 2, cc = u & 3;
                CP_ASYNC16(bb + swz(r, cc),
                           Whhp + (size_t)(bn0 + r) * KB + kb0 + cc * 8);
            }
        };

        load_chunk(0, 0);
        {
            const float* xsrc = Xp + ((size_t)t * BATCH + bm0) * G4 + bn0;
            #pragma unroll
            for (int k = 0; k < 8; ++k) {
                int idx = tid + 256 * k;        // 2048 quads (64 rows x 32 quads)
                int r = idx >> 5, q = idx & 31;
                CP_ASYNC16(sb + XP_OFF + (uint32_t)idx * 16,
                           xsrc + (size_t)r * G4 + q * 4);
            }
        }
        CP_COMMIT();
        load_chunk(1, 1); CP_COMMIT();
        load_chunk(2, 2); CP_COMMIT();

        for (int c = 0; c < NC; ++c) {
            if (c <= NC - 3)      { CP_WAIT2(); }
            else if (c == NC - 2) { CP_WAIT1(); }
            else                  { CP_WAIT0(); }
            __syncthreads();
            if (c + 3 < NC) { load_chunk(c + 3, (c + 3) & 3); CP_COMMIT(); }

            const uint32_t ab = sb + (c & 3) * STG;
            const uint32_t bb = ab + A_BYTES;
            #pragma unroll
            for (int ks = 0; ks < 2; ++ks) {
                uint32_t afr[MA][4];
                #pragma unroll
                for (int ma = 0; ma < MA; ++ma) {
                    int row = wm * WM + ma * 16 + (lid & 15);
                    int cc  = 2 * ks + (lid >> 4);
                    LDMX4(afr[ma][0], afr[ma][1], afr[ma][2], afr[ma][3],
                          ab + swz(row, cc));
                }
                uint32_t bfr[NA][2];
                #pragma unroll
                for (int np = 0; np < NA / 2; ++np) {
                    int row = wn * WN + np * 16 + (lid & 15);
                    int cc  = 2 * ks + (lid >> 4);
                    uint32_t r0, r1, r2, r3;
                    LDMX4(r0, r1, r2, r3, bb + swz(row, cc));
                    bfr[2 * np + 0][0] = r0; bfr[2 * np + 1][0] = r1;
                    bfr[2 * np + 0][1] = r2; bfr[2 * np + 1][1] = r3;
                }
                #pragma unroll
                for (int ma = 0; ma < MA; ++ma)
                    #pragma unroll
                    for (int na = 0; na < NA; ++na)
                        MMA16816(acc[ma][na], afr[ma], bfr[na]);
            }
        }

        const int g  = lid >> 2;
        const int tg = lid & 3;
        #pragma unroll
        for (int ma = 0; ma < MA; ++ma) {
            #pragma unroll
            for (int na = 0; na < NA; ++na) {
                const int col = wn * WN + na * 8 + tg * 2;
                const int r0  = wm * WM + ma * 16 + g;
                const int r1  = r0 + 8;
                st[r0 * BNP + col]     = acc[ma][na][0];
                st[r0 * BNP + col + 1] = acc[ma][na][1];
                st[r1 * BNP + col]     = acc[ma][na][2];
                st[r1 * BNP + col + 1] = acc[ma][na][3];
            }
        }
        __syncthreads();

        float* hsrow = hs + (size_t)t * BH;
        #pragma unroll
        for (int k = 0; k < 8; ++k) {
            int idx = tid + 256 * k;
            int r = idx >> 5, jj = idx & 31;
            float4 gq = *reinterpret_cast<const float4*>(st + r * BNP + 4 * jj);
            float4 xq = *reinterpret_cast<const float4*>(xp_s + idx * 4);
            float gi = sigmf(gq.x + xq.x);
            float gf = sigmf(gq.y + xq.y);
            float gg = tanhf(gq.z + xq.z);
            float go = sigmf(gq.w + xq.w);
            float cv = gf * c_reg[k] + gi * gg;
            c_reg[k] = cv;
            float h = go * tanhf(cv);
            int b = bm0 + r;
            hsrow[b * HID + j0 + jj] = h;
            hpn[(size_t)b * KA + j0 + jj] = __float2half(h);
        }

        __syncthreads();
        if (tid == 0) {
            __threadfence();
            unsigned a = atomicAdd(&g_bar_cnt, 1);
            if (a == 127u) {
                atomicExch(&g_bar_cnt, 0);
                __threadfence();
                atomicAdd(&g_bar_gen, 1);
            } else {
                unsigned target = bar_base + (unsigned)t + 1u;
                while ((int)(ld_acq(&g_bar_gen) - target) < 0) __nanosleep(64);
            }
        }
        __syncthreads();
    }
}

// ---------------- conversion kernels ---------------------------------------
__global__ void conv_act(const float* __restrict__ W, __half* __restrict__ Wp, int total)
{
    int i = blockIdx.x * blockDim.x + threadIdx.x;
    if (i >= total) return;
    Wp[i] = __float2half(W[i]);
}

// single-fp16 gate-interleaved permutation: orig row q*1024+j -> j*4+q
__global__ void conv_act_perm(const float* __restrict__ W, __half* __restrict__ Wp, int total)
{
    int i = blockIdx.x * blockDim.x + threadIdx.x;
    if (i >= total) return;
    int r = i >> 10, k = i & 1023;
    int q = r >> 10, j = r & 1023;
    Wp[(size_t)(j * 4 + q) * KA + k] = __float2half(W[i]);
}

// 2-term split, gate-interleaved (recurrence weights only)
__global__ void conv_wt_perm(const float* __restrict__ W, __half* __restrict__ Wp, int total)
{
    int i = blockIdx.x * blockDim.x + threadIdx.x;
    if (i >= total) return;
    int r = i >> 10, k = i & 1023;
    int q = r >> 10, j = r & 1023;
    float w = W[i];
    __half hi = __float2half(w);
    float lo = w - __half2float(hi);
    size_t base = (size_t)(j * 4 + q) * KB;
    Wp[base + k]        = hi;
    Wp[base + 1024 + k] = __float2half(lo);
}

__global__ void init_misc()
{
    if (threadIdx.x == 0 && blockIdx.x == 0) {
        g_bar_cnt = 0;
        g_bar_gen = 0;
    }
}

__global__ void bias_combine_perm(const float* __restrict__ b_ih, const float* __restrict__ b_hh)
{
    int i = blockIdx.x * blockDim.x + threadIdx.x;   // over G4
    if (i >= G4) return;
    int q = i >> 10, j = i & 1023;
    g_bias[j * 4 + q] = b_ih[i] + b_hh[i];
}

__global__ void softmax128(const float* __restrict__ W)
{
    int row = blockIdx.x;
    int t = threadIdx.x;
    int lane = t & 31, warp = t >> 5;
    __shared__ float red[4];
    float v = W[row * SEQ + t];

    float m = v;
    #pragma unroll
    for (int o = 16; o > 0; o >>= 1) m = fmaxf(m, __shfl_xor_sync(0xffffffffu, m, o));
    if (lane == 0) red[warp] = m;
    __syncthreads();
    m = fmaxf(fmaxf(red[0], red[1]), fmaxf(red[2], red[3]));
    __syncthreads();

    float e = expf(v - m);
    float s = e;
    #pragma unroll
    for (int o = 16; o > 0; o >>= 1) s += __shfl_xor_sync(0xffffffffu, s, o);
    if (lane == 0) red[warp] = s;
    __syncthreads();
    s = red[0] + red[1] + red[2] + red[3];
    g_A[row * SEQ + t] = e / s;
}

// att16 = fp16(softmax(attnW) @ hs), written directly into g_Xbf
__global__ __launch_bounds__(128)
void attn_apply_fused()
{
    __shared__ float Asub[32][SEQ + 1];
    const int tid = threadIdx.x;
    const int n = blockIdx.x * 128 + tid;     // over BH (b*1024 + h)
    const int x0 = blockIdx.y * 32;

    for (int i = tid; i < 32 * SEQ; i += 128) {
        int xx = i >> 7;
        int y = i & 127;
        Asub[xx][y] = g_A[(x0 + xx) * SEQ + y];
    }
    __syncthreads();

    float acc[32];
    #pragma unroll
    for (int xx = 0; xx < 32; ++xx) acc[xx] = 0.f;

    for (int y = 0; y < SEQ; ++y) {
        float v = g_hs[(size_t)y * BH + n];
        #pragma unroll
        for (int xx = 0; xx < 32; ++xx)
            acc[xx] = fmaf(Asub[xx][y], v, acc[xx]);
    }

    const int b = n >> 10;
    const int h = n & 1023;
    #pragma unroll
    for (int xx = 0; xx < 32; ++xx)
        g_Xbf[(size_t)((x0 + xx) * BATCH + b) * KA + h] = __float2half(acc[xx]);
}

// ---------------- launch ----------------------------------------------------
extern "C" void kernel_launch(void* const* d_in, const int* in_sizes, int n_in,
                              void* d_out, int out_size)
{
    const float* inputs = (const float*)d_in[0];
    const float* h0     = (const float*)d_in[1];
    const float* c0     = (const float*)d_in[2];
    const float* W_ih   = (const float*)d_in[3];
    const float* W_hh   = (const float*)d_in[4];
    const float* b_ih   = (const float*)d_in[5];
    const float* b_hh   = (const float*)d_in[6];
    const float* attnW  = (const float*)d_in[7];
    const float* linW   = (const float*)d_in[8];
    const float* linb   = (const float*)d_in[9];
    float* out = (float*)d_out;

    void* p;
    cudaGetSymbolAddress(&p, g_Xp);    float* Xp    = (float*)p;
    cudaGetSymbolAddress(&p, g_hs);    float* hsb   = (float*)p;
    cudaGetSymbolAddress(&p, g_bias);  float* biasc = (float*)p;
    cudaGetSymbolAddress(&p, g_Xbf);   __half* Xbf   = (__half*)p;
    cudaGetSymbolAddress(&p, g_Wihp);  __half* Wihp  = (__half*)p;
    cudaGetSymbolAddress(&p, g_Whhp);  __half* Whhp  = (__half*)p;
    cudaGetSymbolAddress(&p, g_linWp); __half* linWp = (__half*)p;
    cudaGetSymbolAddress(&p, g_hp);    __half* hp    = (__half*)p;

    const int SMEM_BIG  = 4 * ((128 + 128) * BK * 2);                 // 65536
    const int SMEM_PERS = 4 * ((64 + 128) * BK * 2) + 64 * 128 * 4;   // 81920

    cudaFuncSetAttribute((const void*)gemm_mma<128, 128, 2, 4, KA>,
                         cudaFuncAttributeMaxDynamicSharedMemorySize, SMEM_BIG);
    cudaFuncSetAttribute((const void*)lstm_persistent,
                         cudaFuncAttributeMaxDynamicSharedMemorySize, SMEM_PERS);

    conv_act<<<(SEQ * BATCH * 1024) / 256, 256>>>(inputs, Xbf, SEQ * BATCH * 1024); // 0
    conv_act_perm<<<(G4 * 1024) / 256, 256>>>(W_ih, Wihp, G4 * 1024);               // 1
    bias_combine_perm<<<(G4 + 255) / 256, 256>>>(b_ih, b_hh);                       // 2
    conv_wt_perm<<<(G4 * 1024) / 256, 256>>>(W_hh, Whhp, G4 * 1024);                // 3
    conv_act<<<(BATCH * 1024) / 256, 256>>>(h0, hp, BATCH * 1024);                  // 4

    // 5: Xp = X16 @ W_ih16^T + bias'   (single fp16 weights, K=1024)
    gemm_mma<128, 128, 2, 4, KA>
        <<<dim3(G4 / 128, (SEQ * BATCH) / 128), 256, SMEM_BIG>>>(
        Xbf, Wihp, biasc, Xp, G4, 1);

    init_misc<<<1, 32>>>();                                                          // 6
    softmax128<<<SEQ, SEQ>>>(attnW);                                                 // 7

    // 8: persistent recurrence (2-term weights, all 128 steps, c in registers)
    lstm_persistent<<<dim3(G4 / 128, BATCH / 64), 256, SMEM_PERS>>>(
        Whhp, Xp, c0, hsb, hp);

    // 9: attention mix -> fp16 att directly into Xbf
    attn_apply_fused<<<dim3(BH / 128, SEQ / 32), 128>>>();

    conv_act<<<(OUTD * 1024) / 256, 256>>>(linW, linWp, OUTD * 1024);                // 10

    // 11: out = att16 @ linW16^T + linb   (single fp16 weights, K=1024)
    gemm_mma<128, 128, 2, 4, KA>
        <<<dim3(OUTD / 128, (SEQ * BATCH) / 128), 256, SMEM_BIG>>>(
        Xbf, linWp, linb, out, OUTD, 1);
}

// round 10
// speedup vs baseline: 1.7315x; 1.7315x over previous
#include <cuda_runtime.h>
#include <cuda_fp16.h>
#include <math.h>
#include <stdint.h>

// Problem dims
#define SEQ   128
#define BATCH 256
#define IND   1024
#define HID   1024
#define OUTD  1024
#define G4    4096
#define BH    (BATCH*HID)
#define KA    1024            // activations: fp16, rounded once
#define KB    2048            // recurrence weights: [hi | lo] fp16 split
#define BK    32

// ---------------- scratch (device globals) ---------------------------------
__device__ float g_Xp[(size_t)SEQ * BATCH * G4];     // 512 MB (gate-interleaved cols)
__device__ float g_hs[(size_t)SEQ * BATCH * HID];    // 128 MB
__device__ float g_A[SEQ * SEQ];
__device__ float g_bias[G4];                          // gate-interleaved
__device__ __half g_Xbf[(size_t)SEQ * BATCH * KA];    // 64 MB: X16 then att16
__device__ __half g_Wihp[(size_t)G4 * KA];            // 8 MB (single fp16, gate-perm)
__device__ __half g_Whhp[(size_t)G4 * KB];            // 16 MB (2-term split, gate-perm)
__device__ __half g_linWp[(size_t)OUTD * KA];         // 2 MB (single fp16)
__device__ __half g_hp[(size_t)2 * BATCH * KA];       // double-buffered h16
__device__ unsigned g_bar_cnt;
__device__ unsigned g_bar_gen;

// ---------------- PTX helpers ----------------------------------------------
__device__ __forceinline__ uint32_t smem_u32(const void* p) {
    uint32_t a;
    asm("{ .reg .u64 t; cvta.to.shared.u64 t, %1; cvt.u32.u64 %0, t; }"
        : "=r"(a) : "l"(p));
    return a;
}

#define CP_ASYNC16(dst, src) \
    asm volatile("cp.async.cg.shared.global [%0], [%1], 16;" :: "r"(dst), "l"(src))
#define CP_COMMIT()  asm volatile("cp.async.commit_group;" ::: "memory")
#define CP_WAIT2()   asm volatile("cp.async.wait_group 2;" ::: "memory")
#define CP_WAIT1()   asm volatile("cp.async.wait_group 1;" ::: "memory")
#define CP_WAIT0()   asm volatile("cp.async.wait_group 0;" ::: "memory")

#define LDMX4(r0, r1, r2, r3, addr) \
    asm volatile("ldmatrix.sync.aligned.m8n8.x4.shared.b16 {%0,%1,%2,%3}, [%4];" \
                 : "=r"(r0), "=r"(r1), "=r"(r2), "=r"(r3) : "r"(addr))

#define MMA16816(d, a, b) \
    asm volatile("mma.sync.aligned.m16n8k16.row.col.f32.f16.f16.f32 " \
                 "{%0,%1,%2,%3}, {%4,%5,%6,%7}, {%8,%9}, {%0,%1,%2,%3};" \
                 : "+f"((d)[0]), "+f"((d)[1]), "+f"((d)[2]), "+f"((d)[3]) \
                 : "r"((a)[0]), "r"((a)[1]), "r"((a)[2]), "r"((a)[3]), \
                   "r"((b)[0]), "r"((b)[1]))

// swizzled 16B-chunk byte offset, 64B rows (4 chunks of 8 fp16) — big GEMMs
__device__ __forceinline__ uint32_t swz(int row, int c) {
    return (uint32_t)((row * 4 + (c ^ ((row >> 1) & 3))) * 16);
}

// swizzled 16B-chunk byte offset, 128B rows (8 chunks) — recurrence BK=64
__device__ __forceinline__ uint32_t swz64(int row, int c) {
    return (uint32_t)((row * 8 + (c ^ (row & 7))) * 16);
}

__device__ __forceinline__ float sigmf(float x) {
    return 1.0f / (1.0f + __expf(-x));
}

__device__ __forceinline__ unsigned ld_acq(unsigned* p) {
    unsigned v;
    asm volatile("ld.acquire.gpu.global.u32 %0, [%1];" : "=r"(v) : "l"(p) : "memory");
    return v;
}

// ---------------- fp16 HMMA GEMM (big one-shot GEMMs) -----------------------
// C[M,N] = A16[M,KA] @ B16[N,KBB]^T (+bias), fp32 accum; A chunk index wraps
// mod KA. 256 threads = 8 warps (WGM x WGN). BK=32, 4-stage cp.async.
template<int BM, int BN, int WGM, int WGN, int KBB>
__global__ __launch_bounds__(256)
void gemm_mma(const __half* __restrict__ A,
              const __half* __restrict__ B,
              const float* __restrict__ bias,
              float* __restrict__ C,
              int N, int hasBias)
{
    constexpr int NCC = KBB / BK;
    constexpr int WM = BM / WGM;
    constexpr int WN = BN / WGN;
    constexpr int MA = WM / 16;
    constexpr int NA = WN / 8;
    constexpr int A_BYTES = BM * BK * 2;
    constexpr int B_BYTES = BN * BK * 2;
    constexpr int STAGE   = A_BYTES + B_BYTES;

    extern __shared__ __align__(128) char smem[];
    const uint32_t sb = smem_u32(smem);

    const int tid = threadIdx.x;
    const int wid = tid >> 5;
    const int lid = tid & 31;
    const int g   = lid >> 2;
    const int tg  = lid & 3;
    const int wm  = wid / WGN;
    const int wn  = wid % WGN;
    const int bm0 = blockIdx.y * BM;
    const int bn0 = blockIdx.x * BN;

    float acc[MA][NA][4];
    #pragma unroll
    for (int i = 0; i < MA; ++i)
        #pragma unroll
        for (int j = 0; j < NA; ++j)
            #pragma unroll
            for (int q = 0; q < 4; ++q) acc[i][j][q] = 0.f;

    auto load_tile = [&](int c, int s) {
        const uint32_t abase = sb + s * STAGE;
        const uint32_t bbase = abase + A_BYTES;
        const int ka0 = (c & (KA / BK - 1)) * BK;   // A wraps
        const int kb0 = c * BK;
        #pragma unroll
        for (int u = tid; u < BM * 4; u += 256) {
            int r = u >> 2, cc = u & 3;
            CP_ASYNC16(abase + swz(r, cc),
                       A + (size_t)(bm0 + r) * KA + ka0 + cc * 8);
        }
        #pragma unroll
        for (int u = tid; u < BN * 4; u += 256) {
            int r = u >> 2, cc = u & 3;
            CP_ASYNC16(bbase + swz(r, cc),
                       B + (size_t)(bn0 + r) * KBB + kb0 + cc * 8);
        }
    };

    load_tile(0, 0); CP_COMMIT();
    load_tile(1, 1); CP_COMMIT();
    load_tile(2, 2); CP_COMMIT();

    for (int c = 0; c < NCC; ++c) {
        if (c <= NCC - 3)      { CP_WAIT2(); }
        else if (c == NCC - 2) { CP_WAIT1(); }
        else                   { CP_WAIT0(); }
        __syncthreads();
        if (c + 3 < NCC) { load_tile(c + 3, (c + 3) & 3); CP_COMMIT(); }

        const uint32_t abase = sb + (c & 3) * STAGE;
        const uint32_t bbase = abase + A_BYTES;

        #pragma unroll
        for (int ks = 0; ks < 2; ++ks) {
            uint32_t afr[MA][4];
            #pragma unroll
            for (int ma = 0; ma < MA; ++ma) {
                int row = wm * WM + ma * 16 + (lid & 15);
                int cc  = 2 * ks + (lid >> 4);
                LDMX4(afr[ma][0], afr[ma][1], afr[ma][2], afr[ma][3],
                      abase + swz(row, cc));
            }
            uint32_t bfr[NA][2];
            #pragma unroll
            for (int np = 0; np < NA / 2; ++np) {
                int row = wn * WN + np * 16 + (lid & 15);
                int cc  = 2 * ks + (lid >> 4);
                uint32_t r0, r1, r2, r3;
                LDMX4(r0, r1, r2, r3, bbase + swz(row, cc));
                bfr[2 * np + 0][0] = r0; bfr[2 * np + 1][0] = r1;
                bfr[2 * np + 0][1] = r2; bfr[2 * np + 1][1] = r3;
            }
            #pragma unroll
            for (int ma = 0; ma < MA; ++ma)
                #pragma unroll
                for (int na = 0; na < NA; ++na)
                    MMA16816(acc[ma][na], afr[ma], bfr[na]);
        }
    }

    #pragma unroll
    for (int ma = 0; ma < MA; ++ma) {
        #pragma unroll
        for (int na = 0; na < NA; ++na) {
            const int col = bn0 + wn * WN + na * 8 + tg * 2;
            const int r0  = bm0 + wm * WM + ma * 16 + g;
            const int r1  = r0 + 8;
            float2 v0 = make_float2(acc[ma][na][0], acc[ma][na][1]);
            float2 v1 = make_float2(acc[ma][na][2], acc[ma][na][3]);
            if (hasBias) {
                float2 bv = *reinterpret_cast<const float2*>(bias + col);
                v0.x += bv.x; v0.y += bv.y; v1.x += bv.x; v1.y += bv.y;
            }
            *reinterpret_cast<float2*>(C + (size_t)r0 * N + col) = v0;
            *reinterpret_cast<float2*>(C + (size_t)r1 * N + col) = v1;
        }
    }
}

// ---------------- persistent LSTM recurrence (BK=64) ------------------------
// 128 CTAs (grid 32x4), all resident. Per step: 64x128 tile of
// gates = h16 @ W_hh'^T (KB=2048, A wraps mod 1024), BK=64 chunks (32 syncs
// instead of 64), Xp[t] tile prefetched, fused pointwise with c-state in
// registers, then software grid barrier.
__global__ __launch_bounds__(256)
void lstm_persistent(const __half* __restrict__ Whhp,
                     const float* __restrict__ Xp,
                     const float* __restrict__ c0,
                     float* __restrict__ hs,
                     __half* __restrict__ hp)
{
    constexpr int BKR = 64;
    constexpr int NC  = KB / BKR;               // 32 chunks
    constexpr int BM = 64, BN = 128, WGN = 4;
    constexpr int WM = 32, WN = 32, MA = 2, NA = 4;
    constexpr int A_BYTES = BM * BKR * 2;       // 8192
    constexpr int B_BYTES = BN * BKR * 2;       // 16384
    constexpr int STG     = A_BYTES + B_BYTES;  // 24576
    constexpr int XP_OFF  = 4 * STG;            // 98304
    constexpr int BNP     = BN + 4;

    extern __shared__ __align__(128) char smem[];
    const uint32_t sb = smem_u32(smem);
    float* st   = reinterpret_cast<float*>(smem);            // [0, 33792) aliases stages 0-1
    float* xp_s = reinterpret_cast<float*>(smem + XP_OFF);   // [98304, 131072)

    const int tid = threadIdx.x;
    const int wid = tid >> 5;
    const int lid = tid & 31;
    const int wm  = wid / WGN;
    const int wn  = wid % WGN;
    const int bn0 = blockIdx.x * BN;
    const int bm0 = blockIdx.y * BM;
    const int j0  = bn0 >> 2;

    float c_reg[8];
    #pragma unroll
    for (int k = 0; k < 8; ++k) {
        int idx = tid + 256 * k;
        int r = idx >> 5, jj = idx & 31;
        c_reg[k] = c0[(bm0 + r) * HID + j0 + jj];
    }

    unsigned bar_base = 0;
    if (tid == 0) bar_base = ld_acq(&g_bar_gen);

    for (int t = 0; t < SEQ; ++t) {
        const __half* Ap = hp + (size_t)(t & 1) * BATCH * KA;
        __half* hpn = hp + (size_t)((t + 1) & 1) * BATCH * KA;

        float acc[MA][NA][4];
        #pragma unroll
        for (int i = 0; i < MA; ++i)
            #pragma unroll
            for (int j = 0; j < NA; ++j)
                #pragma unroll
                for (int q = 0; q < 4; ++q) acc[i][j][q] = 0.f;

        auto load_chunk = [&](int c, int s) {
            const uint32_t ab = sb + s * STG;
            const uint32_t bb = ab + A_BYTES;
            const int ka0 = (c & (KA / BKR - 1)) * BKR;
            const int kb0 = c * BKR;
            #pragma unroll
            for (int it = 0; it < 2; ++it) {   // A: 64 rows x 8 chunks = 512
                int u = tid + it * 256;
                int r = u >> 3, cc = u & 7;
                CP_ASYNC16(ab + swz64(r, cc),
                           Ap + (size_t)(bm0 + r) * KA + ka0 + cc * 8);
            }
            #pragma unroll
            for (int it = 0; it < 4; ++it) {   // B: 128 rows x 8 chunks = 1024
                int u = tid + it * 256;
                int r = u >> 3, cc = u & 7;
                CP_ASYNC16(bb + swz64(r, cc),
                           Whhp + (size_t)(bn0 + r) * KB + kb0 + cc * 8);
            }
        };

        load_chunk(0, 0);
        {
            const float* xsrc = Xp + ((size_t)t * BATCH + bm0) * G4 + bn0;
            #pragma unroll
            for (int k = 0; k < 8; ++k) {
                int idx = tid + 256 * k;        // 2048 quads (64 rows x 32 quads)
                int r = idx >> 5, q = idx & 31;
                CP_ASYNC16(sb + XP_OFF + (uint32_t)idx * 16,
                           xsrc + (size_t)r * G4 + q * 4);
            }
        }
        CP_COMMIT();
        load_chunk(1, 1); CP_COMMIT();
        load_chunk(2, 2); CP_COMMIT();

        for (int c = 0; c < NC; ++c) {
            if (c <= NC - 3)      { CP_WAIT2(); }
            else if (c == NC - 2) { CP_WAIT1(); }
            else                  { CP_WAIT0(); }
            __syncthreads();
            if (c + 3 < NC) { load_chunk(c + 3, (c + 3) & 3); CP_COMMIT(); }

            const uint32_t ab = sb + (c & 3) * STG;
            const uint32_t bb = ab + A_BYTES;
            #pragma unroll
            for (int ks = 0; ks < 4; ++ks) {
                uint32_t afr[MA][4];
                #pragma unroll
                for (int ma = 0; ma < MA; ++ma) {
                    int row = wm * WM + ma * 16 + (lid & 15);
                    int cc  = 2 * ks + (lid >> 4);
                    LDMX4(afr[ma][0], afr[ma][1], afr[ma][2], afr[ma][3],
                          ab + swz64(row, cc));
                }
                uint32_t bfr[NA][2];
                #pragma unroll
                for (int np = 0; np < NA / 2; ++np) {
                    int row = wn * WN + np * 16 + (lid & 15);
                    int cc  = 2 * ks + (lid >> 4);
                    uint32_t r0, r1, r2, r3;
                    LDMX4(r0, r1, r2, r3, bb + swz64(row, cc));
                    bfr[2 * np + 0][0] = r0; bfr[2 * np + 1][0] = r1;
                    bfr[2 * np + 0][1] = r2; bfr[2 * np + 1][1] = r3;
                }
                #pragma unroll
                for (int ma = 0; ma < MA; ++ma)
                    #pragma unroll
                    for (int na = 0; na < NA; ++na)
                        MMA16816(acc[ma][na], afr[ma], bfr[na]);
            }
        }

        const int g  = lid >> 2;
        const int tg = lid & 3;
        #pragma unroll
        for (int ma = 0; ma < MA; ++ma) {
            #pragma unroll
            for (int na = 0; na < NA; ++na) {
                const int col = wn * WN + na * 8 + tg * 2;
                const int r0  = wm * WM + ma * 16 + g;
                const int r1  = r0 + 8;
                st[r0 * BNP + col]     = acc[ma][na][0];
                st[r0 * BNP + col + 1] = acc[ma][na][1];
                st[r1 * BNP + col]     = acc[ma][na][2];
                st[r1 * BNP + col + 1] = acc[ma][na][3];
            }
        }
        __syncthreads();

        float* hsrow = hs + (size_t)t * BH;
        #pragma unroll
        for (int k = 0; k < 8; ++k) {
            int idx = tid + 256 * k;
            int r = idx >> 5, jj = idx & 31;
            float4 gq = *reinterpret_cast<const float4*>(st + r * BNP + 4 * jj);
            float4 xq = *reinterpret_cast<const float4*>(xp_s + idx * 4);
            float gi = sigmf(gq.x + xq.x);
            float gf = sigmf(gq.y + xq.y);
            float gg = tanhf(gq.z + xq.z);
            float go = sigmf(gq.w + xq.w);
            float cv = gf * c_reg[k] + gi * gg;
            c_reg[k] = cv;
            float h = go * tanhf(cv);
            int b = bm0 + r;
            hsrow[b * HID + j0 + jj] = h;
            hpn[(size_t)b * KA + j0 + jj] = __float2half(h);
        }

        __syncthreads();
        if (tid == 0) {
            __threadfence();
            unsigned a = atomicAdd(&g_bar_cnt, 1);
            if (a == 127u) {
                atomicExch(&g_bar_cnt, 0);
                __threadfence();
                atomicAdd(&g_bar_gen, 1);
            } else {
                unsigned target = bar_base + (unsigned)t + 1u;
                while ((int)(ld_acq(&g_bar_gen) - target) < 0) __nanosleep(64);
            }
        }
        __syncthreads();
    }
}

// ---------------- conversion kernels ---------------------------------------
__global__ void conv_act(const float* __restrict__ W, __half* __restrict__ Wp, int total)
{
    int i = blockIdx.x * blockDim.x + threadIdx.x;
    if (i >= total) return;
    Wp[i] = __float2half(W[i]);
}

// single-fp16 gate-interleaved permutation: orig row q*1024+j -> j*4+q
__global__ void conv_act_perm(const float* __restrict__ W, __half* __restrict__ Wp, int total)
{
    int i = blockIdx.x * blockDim.x + threadIdx.x;
    if (i >= total) return;
    int r = i >> 10, k = i & 1023;
    int q = r >> 10, j = r & 1023;
    Wp[(size_t)(j * 4 + q) * KA + k] = __float2half(W[i]);
}

// 2-term split, gate-interleaved (recurrence weights only)
__global__ void conv_wt_perm(const float* __restrict__ W, __half* __restrict__ Wp, int total)
{
    int i = blockIdx.x * blockDim.x + threadIdx.x;
    if (i >= total) return;
    int r = i >> 10, k = i & 1023;
    int q = r >> 10, j = r & 1023;
    float w = W[i];
    __half hi = __float2half(w);
    float lo = w - __half2float(hi);
    size_t base = (size_t)(j * 4 + q) * KB;
    Wp[base + k]        = hi;
    Wp[base + 1024 + k] = __float2half(lo);
}

__global__ void init_misc()
{
    if (threadIdx.x == 0 && blockIdx.x == 0) {
        g_bar_cnt = 0;
        g_bar_gen = 0;
    }
}

__global__ void bias_combine_perm(const float* __restrict__ b_ih, const float* __restrict__ b_hh)
{
    int i = blockIdx.x * blockDim.x + threadIdx.x;   // over G4
    if (i >= G4) return;
    int q = i >> 10, j = i & 1023;
    g_bias[j * 4 + q] = b_ih[i] + b_hh[i];
}

__global__ void softmax128(const float* __restrict__ W)
{
    int row = blockIdx.x;
    int t = threadIdx.x;
    int lane = t & 31, warp = t >> 5;
    __shared__ float red[4];
    float v = W[row * SEQ + t];

    float m = v;
    #pragma unroll
    for (int o = 16; o > 0; o >>= 1) m = fmaxf(m, __shfl_xor_sync(0xffffffffu, m, o));
    if (lane == 0) red[warp] = m;
    __syncthreads();
    m = fmaxf(fmaxf(red[0], red[1]), fmaxf(red[2], red[3]));
    __syncthreads();

    float e = expf(v - m);
    float s = e;
    #pragma unroll
    for (int o = 16; o > 0; o >>= 1) s += __shfl_xor_sync(0xffffffffu, s, o);
    if (lane == 0) red[warp] = s;
    __syncthreads();
    s = red[0] + red[1] + red[2] + red[3];
    g_A[row * SEQ + t] = e / s;
}

// att16 = fp16(softmax(attnW) @ hs), written directly into g_Xbf
__global__ __launch_bounds__(128)
void attn_apply_fused()
{
    __shared__ float Asub[32][SEQ + 1];
    const int tid = threadIdx.x;
    const int n = blockIdx.x * 128 + tid;     // over BH (b*1024 + h)
    const int x0 = blockIdx.y * 32;

    for (int i = tid; i < 32 * SEQ; i += 128) {
        int xx = i >> 7;
        int y = i & 127;
        Asub[xx][y] = g_A[(x0 + xx) * SEQ + y];
    }
    __syncthreads();

    float acc[32];
    #pragma unroll
    for (int xx = 0; xx < 32; ++xx) acc[xx] = 0.f;

    for (int y = 0; y < SEQ; ++y) {
        float v = g_hs[(size_t)y * BH + n];
        #pragma unroll
        for (int xx = 0; xx < 32; ++xx)
            acc[xx] = fmaf(Asub[xx][y], v, acc[xx]);
    }

    const int b = n >> 10;
    const int h = n & 1023;
    #pragma unroll
    for (int xx = 0; xx < 32; ++xx)
        g_Xbf[(size_t)((x0 + xx) * BATCH + b) * KA + h] = __float2half(acc[xx]);
}

// ---------------- launch ----------------------------------------------------
extern "C" void kernel_launch(void* const* d_in, const int* in_sizes, int n_in,
                              void* d_out, int out_size)
{
    const float* inputs = (const float*)d_in[0];
    const float* h0     = (const float*)d_in[1];
    const float* c0     = (const float*)d_in[2];
    const float* W_ih   = (const float*)d_in[3];
    const float* W_hh   = (const float*)d_in[4];
    const float* b_ih   = (const float*)d_in[5];
    const float* b_hh   = (const float*)d_in[6];
    const float* attnW  = (const float*)d_in[7];
    const float* linW   = (const float*)d_in[8];
    const float* linb   = (const float*)d_in[9];
    float* out = (float*)d_out;

    void* p;
    cudaGetSymbolAddress(&p, g_Xp);    float* Xp    = (float*)p;
    cudaGetSymbolAddress(&p, g_hs);    float* hsb   = (float*)p;
    cudaGetSymbolAddress(&p, g_bias);  float* biasc = (float*)p;
    cudaGetSymbolAddress(&p, g_Xbf);   __half* Xbf   = (__half*)p;
    cudaGetSymbolAddress(&p, g_Wihp);  __half* Wihp  = (__half*)p;
    cudaGetSymbolAddress(&p, g_Whhp);  __half* Whhp  = (__half*)p;
    cudaGetSymbolAddress(&p, g_linWp); __half* linWp = (__half*)p;
    cudaGetSymbolAddress(&p, g_hp);    __half* hp    = (__half*)p;

    const int SMEM_BIG  = 4 * ((128 + 128) * BK * 2);                 // 65536
    const int SMEM_PERS = 4 * ((64 + 128) * 64 * 2) + 64 * 128 * 4;   // 98304 + 32768 = 131072

    cudaFuncSetAttribute((const void*)gemm_mma<128, 128, 2, 4, KA>,
                         cudaFuncAttributeMaxDynamicSharedMemorySize, SMEM_BIG);
    cudaFuncSetAttribute((const void*)lstm_persistent,
                         cudaFuncAttributeMaxDynamicSharedMemorySize, SMEM_PERS);

    // setup order identical to R8 so conv_wt_perm stays the ncu clock canary
    conv_act<<<(SEQ * BATCH * 1024) / 256, 256>>>(inputs, Xbf, SEQ * BATCH * 1024); // 0
    conv_act_perm<<<(G4 * 1024) / 256, 256>>>(W_ih, Wihp, G4 * 1024);               // 1
    bias_combine_perm<<<(G4 + 255) / 256, 256>>>(b_ih, b_hh);                       // 2
    conv_wt_perm<<<(G4 * 1024) / 256, 256>>>(W_hh, Whhp, G4 * 1024);                // 3 (canary)
    conv_act<<<(BATCH * 1024) / 256, 256>>>(h0, hp, BATCH * 1024);                  // 4

    // 5: Xp = X16 @ W_ih16^T + bias'   (single fp16 weights, K=1024)
    gemm_mma<128, 128, 2, 4, KA>
        <<<dim3(G4 / 128, (SEQ * BATCH) / 128), 256, SMEM_BIG>>>(
        Xbf, Wihp, biasc, Xp, G4, 1);

    init_misc<<<1, 32>>>();                                                          // 6
    softmax128<<<SEQ, SEQ>>>(attnW);                                                 // 7

    // 8: persistent recurrence (BK=64, 2-term weights, c in registers)
    lstm_persistent<<<dim3(G4 / 128, BATCH / 64), 256, SMEM_PERS>>>(
        Whhp, Xp, c0, hsb, hp);

    // 9: attention mix -> fp16 att directly into Xbf
    attn_apply_fused<<<dim3(BH / 128, SEQ / 32), 128>>>();

    conv_act<<<(OUTD * 1024) / 256, 256>>>(linW, linWp, OUTD * 1024);                // 10

    // 11: out = att16 @ linW16^T + linb   (single fp16 weights, K=1024)
    gemm_mma<128, 128, 2, 4, KA>
        <<<dim3(OUTD / 128, (SEQ * BATCH) / 128), 256, SMEM_BIG>>>(
        Xbf, linWp, linb, out, OUTD, 1);
}

// round 12
// speedup vs baseline: 2.2953x; 1.3256x over previous
#include <cuda_runtime.h>
#include <cuda_fp16.h>
#include <math.h>
#include <stdint.h>

// Problem dims
#define SEQ   128
#define BATCH 256
#define IND   1024
#define HID   1024
#define OUTD  1024
#define G4    4096
#define BH    (BATCH*HID)
#define KA    1024            // activations AND all weights: fp16, rounded once
#define BK    32

// ---------------- scratch (device globals) ---------------------------------
__device__ float g_Xp[(size_t)SEQ * BATCH * G4];     // 512 MB (gate-interleaved cols)
__device__ float g_hs[(size_t)SEQ * BATCH * HID];    // 128 MB
__device__ float g_A[SEQ * SEQ];
__device__ float g_bias[G4];                          // gate-interleaved
__device__ __half g_Xbf[(size_t)SEQ * BATCH * KA];    // 64 MB: X16 then att16
__device__ __half g_Wihp[(size_t)G4 * KA];            // 8 MB (single fp16, gate-perm)
__device__ __half g_Whhp[(size_t)G4 * KA];            // 8 MB (single fp16, gate-perm)
__device__ __half g_linWp[(size_t)OUTD * KA];         // 2 MB (single fp16)
__device__ __half g_hp[(size_t)2 * BATCH * KA];       // double-buffered h16
__device__ unsigned g_bar_cnt;
__device__ unsigned g_bar_gen;

// ---------------- PTX helpers ----------------------------------------------
__device__ __forceinline__ uint32_t smem_u32(const void* p) {
    uint32_t a;
    asm("{ .reg .u64 t; cvta.to.shared.u64 t, %1; cvt.u32.u64 %0, t; }"
        : "=r"(a) : "l"(p));
    return a;
}

#define CP_ASYNC16(dst, src) \
    asm volatile("cp.async.cg.shared.global [%0], [%1], 16;" :: "r"(dst), "l"(src))
#define CP_COMMIT()  asm volatile("cp.async.commit_group;" ::: "memory")
#define CP_WAIT2()   asm volatile("cp.async.wait_group 2;" ::: "memory")
#define CP_WAIT1()   asm volatile("cp.async.wait_group 1;" ::: "memory")
#define CP_WAIT0()   asm volatile("cp.async.wait_group 0;" ::: "memory")

#define LDMX4(r0, r1, r2, r3, addr) \
    asm volatile("ldmatrix.sync.aligned.m8n8.x4.shared.b16 {%0,%1,%2,%3}, [%4];" \
                 : "=r"(r0), "=r"(r1), "=r"(r2), "=r"(r3) : "r"(addr))

#define MMA16816(d, a, b) \
    asm volatile("mma.sync.aligned.m16n8k16.row.col.f32.f16.f16.f32 " \
                 "{%0,%1,%2,%3}, {%4,%5,%6,%7}, {%8,%9}, {%0,%1,%2,%3};" \
                 : "+f"((d)[0]), "+f"((d)[1]), "+f"((d)[2]), "+f"((d)[3]) \
                 : "r"((a)[0]), "r"((a)[1]), "r"((a)[2]), "r"((a)[3]), \
                   "r"((b)[0]), "r"((b)[1]))

// swizzled 16B-chunk byte offset, 64B rows (4 chunks of 8 fp16) — big GEMMs
__device__ __forceinline__ uint32_t swz(int row, int c) {
    return (uint32_t)((row * 4 + (c ^ ((row >> 1) & 3))) * 16);
}

// swizzled 16B-chunk byte offset, 128B rows (8 chunks) — recurrence BK=64
__device__ __forceinline__ uint32_t swz64(int row, int c) {
    return (uint32_t)((row * 8 + (c ^ (row & 7))) * 16);
}

__device__ __forceinline__ float sigmf(float x) {
    return 1.0f / (1.0f + __expf(-x));
}

__device__ __forceinline__ unsigned ld_acq(unsigned* p) {
    unsigned v;
    asm volatile("ld.acquire.gpu.global.u32 %0, [%1];" : "=r"(v) : "l"(p) : "memory");
    return v;
}

// ---------------- fp16 HMMA GEMM (big one-shot GEMMs) -----------------------
// C[M,N] = A16[M,KA] @ B16[N,KA]^T (+bias), fp32 accum.
// 256 threads = 8 warps (WGM x WGN). BK=32, 4-stage cp.async.
template<int BM, int BN, int WGM, int WGN>
__global__ __launch_bounds__(256)
void gemm_mma(const __half* __restrict__ A,
              const __half* __restrict__ B,
              const float* __restrict__ bias,
              float* __restrict__ C,
              int N, int hasBias)
{
    constexpr int NCC = KA / BK;
    constexpr int WM = BM / WGM;
    constexpr int WN = BN / WGN;
    constexpr int MA = WM / 16;
    constexpr int NA = WN / 8;
    constexpr int A_BYTES = BM * BK * 2;
    constexpr int B_BYTES = BN * BK * 2;
    constexpr int STAGE   = A_BYTES + B_BYTES;

    extern __shared__ __align__(128) char smem[];
    const uint32_t sb = smem_u32(smem);

    const int tid = threadIdx.x;
    const int wid = tid >> 5;
    const int lid = tid & 31;
    const int g   = lid >> 2;
    const int tg  = lid & 3;
    const int wm  = wid / WGN;
    const int wn  = wid % WGN;
    const int bm0 = blockIdx.y * BM;
    const int bn0 = blockIdx.x * BN;

    float acc[MA][NA][4];
    #pragma unroll
    for (int i = 0; i < MA; ++i)
        #pragma unroll
        for (int j = 0; j < NA; ++j)
            #pragma unroll
            for (int q = 0; q < 4; ++q) acc[i][j][q] = 0.f;

    auto load_tile = [&](int c, int s) {
        const uint32_t abase = sb + s * STAGE;
        const uint32_t bbase = abase + A_BYTES;
        const int k0 = c * BK;
        #pragma unroll
        for (int u = tid; u < BM * 4; u += 256) {
            int r = u >> 2, cc = u & 3;
            CP_ASYNC16(abase + swz(r, cc),
                       A + (size_t)(bm0 + r) * KA + k0 + cc * 8);
        }
        #pragma unroll
        for (int u = tid; u < BN * 4; u += 256) {
            int r = u >> 2, cc = u & 3;
            CP_ASYNC16(bbase + swz(r, cc),
                       B + (size_t)(bn0 + r) * KA + k0 + cc * 8);
        }
    };

    load_tile(0, 0); CP_COMMIT();
    load_tile(1, 1); CP_COMMIT();
    load_tile(2, 2); CP_COMMIT();

    for (int c = 0; c < NCC; ++c) {
        if (c <= NCC - 3)      { CP_WAIT2(); }
        else if (c == NCC - 2) { CP_WAIT1(); }
        else                   { CP_WAIT0(); }
        __syncthreads();
        if (c + 3 < NCC) { load_tile(c + 3, (c + 3) & 3); CP_COMMIT(); }

        const uint32_t abase = sb + (c & 3) * STAGE;
        const uint32_t bbase = abase + A_BYTES;

        #pragma unroll
        for (int ks = 0; ks < 2; ++ks) {
            uint32_t afr[MA][4];
            #pragma unroll
            for (int ma = 0; ma < MA; ++ma) {
                int row = wm * WM + ma * 16 + (lid & 15);
                int cc  = 2 * ks + (lid >> 4);
                LDMX4(afr[ma][0], afr[ma][1], afr[ma][2], afr[ma][3],
                      abase + swz(row, cc));
            }
            uint32_t bfr[NA][2];
            #pragma unroll
            for (int np = 0; np < NA / 2; ++np) {
                int row = wn * WN + np * 16 + (lid & 15);
                int cc  = 2 * ks + (lid >> 4);
                uint32_t r0, r1, r2, r3;
                LDMX4(r0, r1, r2, r3, bbase + swz(row, cc));
                bfr[2 * np + 0][0] = r0; bfr[2 * np + 1][0] = r1;
                bfr[2 * np + 0][1] = r2; bfr[2 * np + 1][1] = r3;
            }
            #pragma unroll
            for (int ma = 0; ma < MA; ++ma)
                #pragma unroll
                for (int na = 0; na < NA; ++na)
                    MMA16816(acc[ma][na], afr[ma], bfr[na]);
        }
    }

    #pragma unroll
    for (int ma = 0; ma < MA; ++ma) {
        #pragma unroll
        for (int na = 0; na < NA; ++na) {
            const int col = bn0 + wn * WN + na * 8 + tg * 2;
            const int r0  = bm0 + wm * WM + ma * 16 + g;
            const int r1  = r0 + 8;
            float2 v0 = make_float2(acc[ma][na][0], acc[ma][na][1]);
            float2 v1 = make_float2(acc[ma][na][2], acc[ma][na][3]);
            if (hasBias) {
                float2 bv = *reinterpret_cast<const float2*>(bias + col);
                v0.x += bv.x; v0.y += bv.y; v1.x += bv.x; v1.y += bv.y;
            }
            *reinterpret_cast<float2*>(C + (size_t)r0 * N + col) = v0;
            *reinterpret_cast<float2*>(C + (size_t)r1 * N + col) = v1;
        }
    }
}

// ---------------- persistent LSTM recurrence (BK=64, K=1024) ----------------
// 128 CTAs (grid 32x4), all resident. Per step: 64x128 tile of
// gates = h16 @ W_hh16^T (K=1024, 16 chunks of 64), Xp[t] tile prefetched,
// fused pointwise with c-state in registers, then software grid barrier.
__global__ __launch_bounds__(256)
void lstm_persistent(const __half* __restrict__ Whhp,
                     const float* __restrict__ Xp,
                     const float* __restrict__ c0,
                     float* __restrict__ hs,
                     __half* __restrict__ hp)
{
    constexpr int BKR = 64;
    constexpr int NC  = KA / BKR;               // 16 chunks
    constexpr int BM = 64, BN = 128, WGN = 4;
    constexpr int WM = 32, WN = 32, MA = 2, NA = 4;
    constexpr int A_BYTES = BM * BKR * 2;       // 8192
    constexpr int B_BYTES = BN * BKR * 2;       // 16384
    constexpr int STG     = A_BYTES + B_BYTES;  // 24576
    constexpr int XP_OFF  = 4 * STG;            // 98304
    constexpr int BNP     = BN + 4;

    extern __shared__ __align__(128) char smem[];
    const uint32_t sb = smem_u32(smem);
    float* st   = reinterpret_cast<float*>(smem);            // [0, 33792) aliases stages 0-1
    float* xp_s = reinterpret_cast<float*>(smem + XP_OFF);   // [98304, 131072)

    const int tid = threadIdx.x;
    const int wid = tid >> 5;
    const int lid = tid & 31;
    const int wm  = wid / WGN;
    const int wn  = wid % WGN;
    const int bn0 = blockIdx.x * BN;
    const int bm0 = blockIdx.y * BM;
    const int j0  = bn0 >> 2;

    float c_reg[8];
    #pragma unroll
    for (int k = 0; k < 8; ++k) {
        int idx = tid + 256 * k;
        int r = idx >> 5, jj = idx & 31;
        c_reg[k] = c0[(bm0 + r) * HID + j0 + jj];
    }

    unsigned bar_base = 0;
    if (tid == 0) bar_base = ld_acq(&g_bar_gen);

    for (int t = 0; t < SEQ; ++t) {
        const __half* Ap = hp + (size_t)(t & 1) * BATCH * KA;
        __half* hpn = hp + (size_t)((t + 1) & 1) * BATCH * KA;

        float acc[MA][NA][4];
        #pragma unroll
        for (int i = 0; i < MA; ++i)
            #pragma unroll
            for (int j = 0; j < NA; ++j)
                #pragma unroll
                for (int q = 0; q < 4; ++q) acc[i][j][q] = 0.f;

        auto load_chunk = [&](int c, int s) {
            const uint32_t ab = sb + s * STG;
            const uint32_t bb = ab + A_BYTES;
            const int k0 = c * BKR;
            #pragma unroll
            for (int it = 0; it < 2; ++it) {   // A: 64 rows x 8 chunks = 512
                int u = tid + it * 256;
                int r = u >> 3, cc = u & 7;
                CP_ASYNC16(ab + swz64(r, cc),
                           Ap + (size_t)(bm0 + r) * KA + k0 + cc * 8);
            }
            #pragma unroll
            for (int it = 0; it < 4; ++it) {   // B: 128 rows x 8 chunks = 1024
                int u = tid + it * 256;
                int r = u >> 3, cc = u & 7;
                CP_ASYNC16(bb + swz64(r, cc),
                           Whhp + (size_t)(bn0 + r) * KA + k0 + cc * 8);
            }
        };

        load_chunk(0, 0);
        {
            const float* xsrc = Xp + ((size_t)t * BATCH + bm0) * G4 + bn0;
            #pragma unroll
            for (int k = 0; k < 8; ++k) {
                int idx = tid + 256 * k;        // 2048 quads (64 rows x 32 quads)
                int r = idx >> 5, q = idx & 31;
                CP_ASYNC16(sb + XP_OFF + (uint32_t)idx * 16,
                           xsrc + (size_t)r * G4 + q * 4);
            }
        }
        CP_COMMIT();
        load_chunk(1, 1); CP_COMMIT();
        load_chunk(2, 2); CP_COMMIT();

        for (int c = 0; c < NC; ++c) {
            if (c <= NC - 3)      { CP_WAIT2(); }
            else if (c == NC - 2) { CP_WAIT1(); }
            else                  { CP_WAIT0(); }
            __syncthreads();
            if (c + 3 < NC) { load_chunk(c + 3, (c + 3) & 3); CP_COMMIT(); }

            const uint32_t ab = sb + (c & 3) * STG;
            const uint32_t bb = ab + A_BYTES;
            #pragma unroll
            for (int ks = 0; ks < 4; ++ks) {
                uint32_t afr[MA][4];
                #pragma unroll
                for (int ma = 0; ma < MA; ++ma) {
                    int row = wm * WM + ma * 16 + (lid & 15);
                    int cc  = 2 * ks + (lid >> 4);
                    LDMX4(afr[ma][0], afr[ma][1], afr[ma][2], afr[ma][3],
                          ab + swz64(row, cc));
                }
                uint32_t bfr[NA][2];
                #pragma unroll
                for (int np = 0; np < NA / 2; ++np) {
                    int row = wn * WN + np * 16 + (lid & 15);
                    int cc  = 2 * ks + (lid >> 4);
                    uint32_t r0, r1, r2, r3;
                    LDMX4(r0, r1, r2, r3, bb + swz64(row, cc));
                    bfr[2 * np + 0][0] = r0; bfr[2 * np + 1][0] = r1;
                    bfr[2 * np + 0][1] = r2; bfr[2 * np + 1][1] = r3;
                }
                #pragma unroll
                for (int ma = 0; ma < MA; ++ma)
                    #pragma unroll
                    for (int na = 0; na < NA; ++na)
                        MMA16816(acc[ma][na], afr[ma], bfr[na]);
            }
        }

        const int g  = lid >> 2;
        const int tg = lid & 3;
        #pragma unroll
        for (int ma = 0; ma < MA; ++ma) {
            #pragma unroll
            for (int na = 0; na < NA; ++na) {
                const int col = wn * WN + na * 8 + tg * 2;
                const int r0  = wm * WM + ma * 16 + g;
                const int r1  = r0 + 8;
                st[r0 * BNP + col]     = acc[ma][na][0];
                st[r0 * BNP + col + 1] = acc[ma][na][1];
                st[r1 * BNP + col]     = acc[ma][na][2];
                st[r1 * BNP + col + 1] = acc[ma][na][3];
            }
        }
        __syncthreads();

        float* hsrow = hs + (size_t)t * BH;
        #pragma unroll
        for (int k = 0; k < 8; ++k) {
            int idx = tid + 256 * k;
            int r = idx >> 5, jj = idx & 31;
            float4 gq = *reinterpret_cast<const float4*>(st + r * BNP + 4 * jj);
            float4 xq = *reinterpret_cast<const float4*>(xp_s + idx * 4);
            float gi = sigmf(gq.x + xq.x);
            float gf = sigmf(gq.y + xq.y);
            float gg = tanhf(gq.z + xq.z);
            float go = sigmf(gq.w + xq.w);
            float cv = gf * c_reg[k] + gi * gg;
            c_reg[k] = cv;
            float h = go * tanhf(cv);
            int b = bm0 + r;
            hsrow[b * HID + j0 + jj] = h;
            hpn[(size_t)b * KA + j0 + jj] = __float2half(h);
        }

        __syncthreads();
        if (tid == 0) {
            __threadfence();
            unsigned a = atomicAdd(&g_bar_cnt, 1);
            if (a == 127u) {
                atomicExch(&g_bar_cnt, 0);
                __threadfence();
                atomicAdd(&g_bar_gen, 1);
            } else {
                unsigned target = bar_base + (unsigned)t + 1u;
                while ((int)(ld_acq(&g_bar_gen) - target) < 0) __nanosleep(64);
            }
        }
        __syncthreads();
    }
}

// ---------------- conversion kernels ---------------------------------------
__global__ void conv_act(const float* __restrict__ W, __half* __restrict__ Wp, int total)
{
    int i = blockIdx.x * blockDim.x + threadIdx.x;
    if (i >= total) return;
    Wp[i] = __float2half(W[i]);
}

// single-fp16 gate-interleaved permutation: orig row q*1024+j -> j*4+q
__global__ void conv_act_perm(const float* __restrict__ W, __half* __restrict__ Wp, int total)
{
    int i = blockIdx.x * blockDim.x + threadIdx.x;
    if (i >= total) return;
    int r = i >> 10, k = i & 1023;
    int q = r >> 10, j = r & 1023;
    Wp[(size_t)(j * 4 + q) * KA + k] = __float2half(W[i]);
}

__global__ void init_misc()
{
    if (threadIdx.x == 0 && blockIdx.x == 0) {
        g_bar_cnt = 0;
        g_bar_gen = 0;
    }
}

__global__ void bias_combine_perm(const float* __restrict__ b_ih, const float* __restrict__ b_hh)
{
    int i = blockIdx.x * blockDim.x + threadIdx.x;   // over G4
    if (i >= G4) return;
    int q = i >> 10, j = i & 1023;
    g_bias[j * 4 + q] = b_ih[i] + b_hh[i];
}

__global__ void softmax128(const float* __restrict__ W)
{
    int row = blockIdx.x;
    int t = threadIdx.x;
    int lane = t & 31, warp = t >> 5;
    __shared__ float red[4];
    float v = W[row * SEQ + t];

    float m = v;
    #pragma unroll
    for (int o = 16; o > 0; o >>= 1) m = fmaxf(m, __shfl_xor_sync(0xffffffffu, m, o));
    if (lane == 0) red[warp] = m;
    __syncthreads();
    m = fmaxf(fmaxf(red[0], red[1]), fmaxf(red[2], red[3]));
    __syncthreads();

    float e = expf(v - m);
    float s = e;
    #pragma unroll
    for (int o = 16; o > 0; o >>= 1) s += __shfl_xor_sync(0xffffffffu, s, o);
    if (lane == 0) red[warp] = s;
    __syncthreads();
    s = red[0] + red[1] + red[2] + red[3];
    g_A[row * SEQ + t] = e / s;
}

// att16 = fp16(softmax(attnW) @ hs), written directly into g_Xbf
__global__ __launch_bounds__(128)
void attn_apply_fused()
{
    __shared__ float Asub[32][SEQ + 1];
    const int tid = threadIdx.x;
    const int n = blockIdx.x * 128 + tid;     // over BH (b*1024 + h)
    const int x0 = blockIdx.y * 32;

    for (int i = tid; i < 32 * SEQ; i += 128) {
        int xx = i >> 7;
        int y = i & 127;
        Asub[xx][y] = g_A[(x0 + xx) * SEQ + y];
    }
    __syncthreads();

    float acc[32];
    #pragma unroll
    for (int xx = 0; xx < 32; ++xx) acc[xx] = 0.f;

    for (int y = 0; y < SEQ; ++y) {
        float v = g_hs[(size_t)y * BH + n];
        #pragma unroll
        for (int xx = 0; xx < 32; ++xx)
            acc[xx] = fmaf(Asub[xx][y], v, acc[xx]);
    }

    const int b = n >> 10;
    const int h = n & 1023;
    #pragma unroll
    for (int xx = 0; xx < 32; ++xx)
        g_Xbf[(size_t)((x0 + xx) * BATCH + b) * KA + h] = __float2half(acc[xx]);
}

// ---------------- launch ----------------------------------------------------
extern "C" void kernel_launch(void* const* d_in, const int* in_sizes, int n_in,
                              void* d_out, int out_size)
{
    const float* inputs = (const float*)d_in[0];
    const float* h0     = (const float*)d_in[1];
    const float* c0     = (const float*)d_in[2];
    const float* W_ih   = (const float*)d_in[3];
    const float* W_hh   = (const float*)d_in[4];
    const float* b_ih   = (const float*)d_in[5];
    const float* b_hh   = (const float*)d_in[6];
    const float* attnW  = (const float*)d_in[7];
    const float* linW   = (const float*)d_in[8];
    const float* linb   = (const float*)d_in[9];
    float* out = (float*)d_out;

    void* p;
    cudaGetSymbolAddress(&p, g_Xp);    float* Xp    = (float*)p;
    cudaGetSymbolAddress(&p, g_hs);    float* hsb   = (float*)p;
    cudaGetSymbolAddress(&p, g_bias);  float* biasc = (float*)p;
    cudaGetSymbolAddress(&p, g_Xbf);   __half* Xbf   = (__half*)p;
    cudaGetSymbolAddress(&p, g_Wihp);  __half* Wihp  = (__half*)p;
    cudaGetSymbolAddress(&p, g_Whhp);  __half* Whhp  = (__half*)p;
    cudaGetSymbolAddress(&p, g_linWp); __half* linWp = (__half*)p;
    cudaGetSymbolAddress(&p, g_hp);    __half* hp    = (__half*)p;

    const int SMEM_BIG  = 4 * ((128 + 128) * BK * 2);                 // 65536
    const int SMEM_PERS = 4 * ((64 + 128) * 64 * 2) + 64 * 128 * 4;   // 131072

    cudaFuncSetAttribute((const void*)gemm_mma<128, 128, 2, 4>,
                         cudaFuncAttributeMaxDynamicSharedMemorySize, SMEM_BIG);
    cudaFuncSetAttribute((const void*)lstm_persistent,
                         cudaFuncAttributeMaxDynamicSharedMemorySize, SMEM_PERS);

    conv_act<<<(SEQ * BATCH * 1024) / 256, 256>>>(inputs, Xbf, SEQ * BATCH * 1024); // 0
    conv_act_perm<<<(G4 * 1024) / 256, 256>>>(W_ih, Wihp, G4 * 1024);               // 1
    bias_combine_perm<<<(G4 + 255) / 256, 256>>>(b_ih, b_hh);                       // 2
    conv_act_perm<<<(G4 * 1024) / 256, 256>>>(W_hh, Whhp, G4 * 1024);               // 3 (canary)
    conv_act<<<(BATCH * 1024) / 256, 256>>>(h0, hp, BATCH * 1024);                  // 4

    // 5: Xp = X16 @ W_ih16^T + bias'   (single fp16 weights, K=1024)
    gemm_mma<128, 128, 2, 4>
        <<<dim3(G4 / 128, (SEQ * BATCH) / 128), 256, SMEM_BIG>>>(
        Xbf, Wihp, biasc, Xp, G4, 1);

    init_misc<<<1, 32>>>();                                                          // 6
    softmax128<<<SEQ, SEQ>>>(attnW);                                                 // 7

    // 8: persistent recurrence (single-term fp16 weights, K=1024, BK=64)
    lstm_persistent<<<dim3(G4 / 128, BATCH / 64), 256, SMEM_PERS>>>(
        Whhp, Xp, c0, hsb, hp);

    // 9: attention mix -> fp16 att directly into Xbf
    attn_apply_fused<<<dim3(BH / 128, SEQ / 32), 128>>>();

    conv_act<<<(OUTD * 1024) / 256, 256>>>(linW, linWp, OUTD * 1024);                // 10

    // 11: out = att16 @ linW16^T + linb   (single fp16 weights, K=1024)
    gemm_mma<128, 128, 2, 4>
        <<<dim3(OUTD / 128, (SEQ * BATCH) / 128), 256, SMEM_BIG>>>(
        Xbf, linWp, linb, out, OUTD, 1);
}

// round 14
// speedup vs baseline: 2.4664x; 1.0745x over previous
#include <cuda_runtime.h>
#include <cuda_fp16.h>
#include <math.h>
#include <stdint.h>

// Problem dims
#define SEQ   128
#define BATCH 256
#define IND   1024
#define HID   1024
#define OUTD  1024
#define G4    4096
#define BH    (BATCH*HID)
#define KA    1024            // activations AND weights: fp16, rounded once
#define BK    32

// ---------------- scratch (device globals) ---------------------------------
__device__ float g_Xp[(size_t)SEQ * BATCH * G4];     // 512 MB (gate-interleaved cols)
__device__ float g_hs[(size_t)SEQ * BATCH * HID];    // 128 MB
__device__ float g_A[SEQ * SEQ];
__device__ float g_bias[G4];                          // gate-interleaved
__device__ __half g_Xbf[(size_t)SEQ * BATCH * KA];    // 64 MB: X16 then att16
__device__ __half g_Wihp[(size_t)G4 * KA];            // 8 MB
__device__ __half g_Whhp[(size_t)G4 * KA];            // 8 MB
__device__ __half g_linWp[(size_t)OUTD * KA];         // 2 MB
__device__ __half g_hp[(size_t)2 * BATCH * KA];       // double-buffered h16
__device__ __half g_A2[SEQ * 2 * SEQ];                // softmax(A) 2-term fp16 [hi|lo]
__device__ __half g_hsT[(size_t)BH * SEQ];            // 64 MB: hs transposed fp16 [n][y]
__device__ unsigned g_bar_cnt;
__device__ unsigned g_bar_gen;

// ---------------- PTX helpers ----------------------------------------------
__device__ __forceinline__ uint32_t smem_u32(const void* p) {
    uint32_t a;
    asm("{ .reg .u64 t; cvta.to.shared.u64 t, %1; cvt.u32.u64 %0, t; }"
        : "=r"(a) : "l"(p));
    return a;
}

#define CP_ASYNC16(dst, src) \
    asm volatile("cp.async.cg.shared.global [%0], [%1], 16;" :: "r"(dst), "l"(src))
#define CP_COMMIT()  asm volatile("cp.async.commit_group;" ::: "memory")
#define CP_WAIT2()   asm volatile("cp.async.wait_group 2;" ::: "memory")
#define CP_WAIT1()   asm volatile("cp.async.wait_group 1;" ::: "memory")
#define CP_WAIT0()   asm volatile("cp.async.wait_group 0;" ::: "memory")

#define LDMX4(r0, r1, r2, r3, addr) \
    asm volatile("ldmatrix.sync.aligned.m8n8.x4.shared.b16 {%0,%1,%2,%3}, [%4];" \
                 : "=r"(r0), "=r"(r1), "=r"(r2), "=r"(r3) : "r"(addr))

#define MMA16816(d, a, b) \
    asm volatile("mma.sync.aligned.m16n8k16.row.col.f32.f16.f16.f32 " \
                 "{%0,%1,%2,%3}, {%4,%5,%6,%7}, {%8,%9}, {%0,%1,%2,%3};" \
                 : "+f"((d)[0]), "+f"((d)[1]), "+f"((d)[2]), "+f"((d)[3]) \
                 : "r"((a)[0]), "r"((a)[1]), "r"((a)[2]), "r"((a)[3]), \
                   "r"((b)[0]), "r"((b)[1]))

// swizzled 16B-chunk byte offset, 64B rows (4 chunks of 8 fp16)
__device__ __forceinline__ uint32_t swz(int row, int c) {
    return (uint32_t)((row * 4 + (c ^ ((row >> 1) & 3))) * 16);
}

// swizzled 16B-chunk byte offset, 128B rows (8 chunks) — recurrence BK=64
__device__ __forceinline__ uint32_t swz64(int row, int c) {
    return (uint32_t)((row * 8 + (c ^ (row & 7))) * 16);
}

__device__ __forceinline__ float sigmf(float x) {
    return 1.0f / (1.0f + __expf(-x));
}

__device__ __forceinline__ unsigned ld_acq(unsigned* p) {
    unsigned v;
    asm volatile("ld.acquire.gpu.global.u32 %0, [%1];" : "=r"(v) : "l"(p) : "memory");
    return v;
}

// ---------------- fp16 HMMA GEMM (generalized) ------------------------------
// C[M,N] = A16[M,KAW-wrapped] @ B16[N,KBW-wrapped]^T (+bias), fp32 accum over
// KIT. A chunk index wraps mod KAW, B wraps mod KBW. HOUT: write fp16.
// 256 threads = 8 warps (WGM x WGN). BK=32, 4-stage cp.async.
template<int BM, int BN, int WGM, int WGN, int KAW, int KBW, int KIT, int HOUT>
__global__ __launch_bounds__(256)
void gemm_mma(const __half* __restrict__ A,
              const __half* __restrict__ B,
              const float* __restrict__ bias,
              void* __restrict__ Cv,
              int N, int hasBias)
{
    constexpr int NCC = KIT / BK;
    constexpr int WM = BM / WGM;
    constexpr int WN = BN / WGN;
    constexpr int MA = WM / 16;
    constexpr int NA = WN / 8;
    constexpr int A_BYTES = BM * BK * 2;
    constexpr int B_BYTES = BN * BK * 2;
    constexpr int STAGE   = A_BYTES + B_BYTES;

    extern __shared__ __align__(128) char smem[];
    const uint32_t sb = smem_u32(smem);

    const int tid = threadIdx.x;
    const int wid = tid >> 5;
    const int lid = tid & 31;
    const int g   = lid >> 2;
    const int tg  = lid & 3;
    const int wm  = wid / WGN;
    const int wn  = wid % WGN;
    const int bm0 = blockIdx.y * BM;
    const int bn0 = blockIdx.x * BN;

    float acc[MA][NA][4];
    #pragma unroll
    for (int i = 0; i < MA; ++i)
        #pragma unroll
        for (int j = 0; j < NA; ++j)
            #pragma unroll
            for (int q = 0; q < 4; ++q) acc[i][j][q] = 0.f;

    auto load_tile = [&](int c, int s) {
        const uint32_t abase = sb + s * STAGE;
        const uint32_t bbase = abase + A_BYTES;
        const int ka0 = (c & (KAW / BK - 1)) * BK;
        const int kb0 = (c & (KBW / BK - 1)) * BK;
        #pragma unroll
        for (int u = tid; u < BM * 4; u += 256) {
            int r = u >> 2, cc = u & 3;
            CP_ASYNC16(abase + swz(r, cc),
                       A + (size_t)(bm0 + r) * KAW + ka0 + cc * 8);
        }
        #pragma unroll
        for (int u = tid; u < BN * 4; u += 256) {
            int r = u >> 2, cc = u & 3;
            CP_ASYNC16(bbase + swz(r, cc),
                       B + (size_t)(bn0 + r) * KBW + kb0 + cc * 8);
        }
    };

    load_tile(0, 0); CP_COMMIT();
    load_tile(1, 1); CP_COMMIT();
    load_tile(2, 2); CP_COMMIT();

    for (int c = 0; c < NCC; ++c) {
        if (c <= NCC - 3)      { CP_WAIT2(); }
        else if (c == NCC - 2) { CP_WAIT1(); }
        else                   { CP_WAIT0(); }
        __syncthreads();
        if (c + 3 < NCC) { load_tile(c + 3, (c + 3) & 3); CP_COMMIT(); }

        const uint32_t abase = sb + (c & 3) * STAGE;
        const uint32_t bbase = abase + A_BYTES;

        #pragma unroll
        for (int ks = 0; ks < 2; ++ks) {
            uint32_t afr[MA][4];
            #pragma unroll
            for (int ma = 0; ma < MA; ++ma) {
                int row = wm * WM + ma * 16 + (lid & 15);
                int cc  = 2 * ks + (lid >> 4);
                LDMX4(afr[ma][0], afr[ma][1], afr[ma][2], afr[ma][3],
                      abase + swz(row, cc));
            }
            uint32_t bfr[NA][2];
            #pragma unroll
            for (int np = 0; np < NA / 2; ++np) {
                int row = wn * WN + np * 16 + (lid & 15);
                int cc  = 2 * ks + (lid >> 4);
                uint32_t r0, r1, r2, r3;
                LDMX4(r0, r1, r2, r3, bbase + swz(row, cc));
                bfr[2 * np + 0][0] = r0; bfr[2 * np + 1][0] = r1;
                bfr[2 * np + 0][1] = r2; bfr[2 * np + 1][1] = r3;
            }
            #pragma unroll
            for (int ma = 0; ma < MA; ++ma)
                #pragma unroll
                for (int na = 0; na < NA; ++na)
                    MMA16816(acc[ma][na], afr[ma], bfr[na]);
        }
    }

    #pragma unroll
    for (int ma = 0; ma < MA; ++ma) {
        #pragma unroll
        for (int na = 0; na < NA; ++na) {
            const int col = bn0 + wn * WN + na * 8 + tg * 2;
            const int r0  = bm0 + wm * WM + ma * 16 + g;
            const int r1  = r0 + 8;
            float2 v0 = make_float2(acc[ma][na][0], acc[ma][na][1]);
            float2 v1 = make_float2(acc[ma][na][2], acc[ma][na][3]);
            if (hasBias) {
                float2 bv = *reinterpret_cast<const float2*>(bias + col);
                v0.x += bv.x; v0.y += bv.y; v1.x += bv.x; v1.y += bv.y;
            }
            if constexpr (HOUT) {
                __half* C16 = (__half*)Cv;
                *reinterpret_cast<__half2*>(C16 + (size_t)r0 * N + col) =
                    __floats2half2_rn(v0.x, v0.y);
                *reinterpret_cast<__half2*>(C16 + (size_t)r1 * N + col) =
                    __floats2half2_rn(v1.x, v1.y);
            } else {
                float* C = (float*)Cv;
                *reinterpret_cast<float2*>(C + (size_t)r0 * N + col) = v0;
                *reinterpret_cast<float2*>(C + (size_t)r1 * N + col) = v1;
            }
        }
    }
}

// ---------------- persistent LSTM recurrence (BK=64, K=1024) ----------------
// 128 CTAs (grid 32x4). Weight chunks 0-2 + Xp(t+1) issued PRE-barrier (no h
// dependence); A(h) chunks post-barrier. Double-buffered Xp; st separate.
__global__ __launch_bounds__(256)
void lstm_persistent(const __half* __restrict__ Whhp,
                     const float* __restrict__ Xp,
                     const float* __restrict__ c0,
                     float* __restrict__ hs,
                     __half* __restrict__ hp)
{
    constexpr int BKR = 64;
    constexpr int NC  = KA / BKR;               // 16 chunks
    constexpr int BM = 64, BN = 128, WGN = 4;
    constexpr int WM = 32, WN = 32, MA = 2, NA = 4;
    constexpr int A_BYTES = BM * BKR * 2;       // 8192
    constexpr int B_BYTES = BN * BKR * 2;       // 16384
    constexpr int STG     = A_BYTES + B_BYTES;  // 24576
    constexpr int XP_OFF  = 4 * STG;            // 98304, two 32KB buffers
    constexpr int ST_OFF  = XP_OFF + 2 * 32768; // 163840
    constexpr int BNP     = BN + 4;

    extern __shared__ __align__(128) char smem[];
    const uint32_t sb = smem_u32(smem);
    float* st = reinterpret_cast<float*>(smem + ST_OFF);

    const int tid = threadIdx.x;
    const int wid = tid >> 5;
    const int lid = tid & 31;
    const int wm  = wid / WGN;
    const int wn  = wid % WGN;
    const int bn0 = blockIdx.x * BN;
    const int bm0 = blockIdx.y * BM;
    const int j0  = bn0 >> 2;

    float c_reg[8];
    #pragma unroll
    for (int k = 0; k < 8; ++k) {
        int idx = tid + 256 * k;
        int r = idx >> 5, jj = idx & 31;
        c_reg[k] = c0[(bm0 + r) * HID + j0 + jj];
    }

    auto loadA = [&](const __half* Ap, int c, int s) {
        const uint32_t ab = sb + s * STG;
        const int k0 = c * BKR;
        #pragma unroll
        for (int it = 0; it < 2; ++it) {   // 64 rows x 8 chunks = 512
            int u = tid + it * 256;
            int r = u >> 3, cc = u & 7;
            CP_ASYNC16(ab + swz64(r, cc),
                       Ap + (size_t)(bm0 + r) * KA + k0 + cc * 8);
        }
    };
    auto loadB = [&](int c, int s) {
        const uint32_t bb = sb + s * STG + A_BYTES;
        const int k0 = c * BKR;
        #pragma unroll
        for (int it = 0; it < 4; ++it) {   // 128 rows x 8 chunks = 1024
            int u = tid + it * 256;
            int r = u >> 3, cc = u & 7;
            CP_ASYNC16(bb + swz64(r, cc),
                       Whhp + (size_t)(bn0 + r) * KA + k0 + cc * 8);
        }
    };
    auto loadXp = [&](int t, int buf) {
        const float* xsrc = Xp + ((size_t)t * BATCH + bm0) * G4 + bn0;
        #pragma unroll
        for (int k = 0; k < 8; ++k) {
            int idx = tid + 256 * k;        // 2048 quads
            int r = idx >> 5, q = idx & 31;
            CP_ASYNC16(sb + XP_OFF + (uint32_t)buf * 32768 + (uint32_t)idx * 16,
                       xsrc + (size_t)r * G4 + q * 4);
        }
    };

    unsigned bar_base = 0;
    if (tid == 0) bar_base = ld_acq(&g_bar_gen);

    // pre-loop "pre-barrier" block for t=0
    loadB(0, 0); CP_COMMIT();
    loadB(1, 1); CP_COMMIT();
    loadB(2, 2); loadXp(0, 0); CP_COMMIT();

    for (int t = 0; t < SEQ; ++t) {
        const __half* Ap = hp + (size_t)(t & 1) * BATCH * KA;
        __half* hpn = hp + (size_t)((t + 1) & 1) * BATCH * KA;
        float* xp_s = reinterpret_cast<float*>(smem + XP_OFF + (t & 1) * 32768);

        // post-barrier A loads (depend on h_t / hp buffer)
        loadA(Ap, 0, 0); CP_COMMIT();
        loadA(Ap, 1, 1); CP_COMMIT();
        loadA(Ap, 2, 2); CP_COMMIT();

        float acc[MA][NA][4];
        #pragma unroll
        for (int i = 0; i < MA; ++i)
            #pragma unroll
            for (int j = 0; j < NA; ++j)
                #pragma unroll
                for (int q = 0; q < 4; ++q) acc[i][j][q] = 0.f;

        for (int c = 0; c < NC; ++c) {
            if (c <= NC - 3)      { CP_WAIT2(); }
            else if (c == NC - 2) { CP_WAIT1(); }
            else                  { CP_WAIT0(); }
            __syncthreads();
            if (c + 3 < NC) {
                loadA(Ap, c + 3, (c + 3) & 3);
                loadB(c + 3, (c + 3) & 3);
                CP_COMMIT();
            }

            const uint32_t ab = sb + (c & 3) * STG;
            const uint32_t bb = ab + A_BYTES;
            #pragma unroll
            for (int ks = 0; ks < 4; ++ks) {
                uint32_t afr[MA][4];
                #pragma unroll
                for (int ma = 0; ma < MA; ++ma) {
                    int row = wm * WM + ma * 16 + (lid & 15);
                    int cc  = 2 * ks + (lid >> 4);
                    LDMX4(afr[ma][0], afr[ma][1], afr[ma][2], afr[ma][3],
                          ab + swz64(row, cc));
                }
                uint32_t bfr[NA][2];
                #pragma unroll
                for (int np = 0; np < NA / 2; ++np) {
                    int row = wn * WN + np * 16 + (lid & 15);
                    int cc  = 2 * ks + (lid >> 4);
                    uint32_t r0, r1, r2, r3;
                    LDMX4(r0, r1, r2, r3, bb + swz64(row, cc));
                    bfr[2 * np + 0][0] = r0; bfr[2 * np + 1][0] = r1;
                    bfr[2 * np + 0][1] = r2; bfr[2 * np + 1][1] = r3;
                }
                #pragma unroll
                for (int ma = 0; ma < MA; ++ma)
                    #pragma unroll
                    for (int na = 0; na < NA; ++na)
                        MMA16816(acc[ma][na], afr[ma], bfr[na]);
            }
        }

        const int g  = lid >> 2;
        const int tg = lid & 3;
        #pragma unroll
        for (int ma = 0; ma < MA; ++ma) {
            #pragma unroll
            for (int na = 0; na < NA; ++na) {
                const int col = wn * WN + na * 8 + tg * 2;
                const int r0  = wm * WM + ma * 16 + g;
                const int r1  = r0 + 8;
                st[r0 * BNP + col]     = acc[ma][na][0];
                st[r0 * BNP + col + 1] = acc[ma][na][1];
                st[r1 * BNP + col]     = acc[ma][na][2];
                st[r1 * BNP + col + 1] = acc[ma][na][3];
            }
        }
        __syncthreads();

        float* hsrow = hs + (size_t)t * BH;
        #pragma unroll
        for (int k = 0; k < 8; ++k) {
            int idx = tid + 256 * k;
            int r = idx >> 5, jj = idx & 31;
            float4 gq = *reinterpret_cast<const float4*>(st + r * BNP + 4 * jj);
            float4 xq = *reinterpret_cast<const float4*>(xp_s + idx * 4);
            float gi = sigmf(gq.x + xq.x);
            float gf = sigmf(gq.y + xq.y);
            float gg = tanhf(gq.z + xq.z);
            float go = sigmf(gq.w + xq.w);
            float cv = gf * c_reg[k] + gi * gg;
            c_reg[k] = cv;
            float h = go * tanhf(cv);
            int b = bm0 + r;
            hsrow[b * HID + j0 + jj] = h;
            hpn[(size_t)b * KA + j0 + jj] = __float2half(h);
        }

        // pre-barrier prefetch for step t+1 (no h dependence)
        if (t + 1 < SEQ) {
            loadB(0, 0); CP_COMMIT();
            loadB(1, 1); CP_COMMIT();
            loadB(2, 2); loadXp(t + 1, (t + 1) & 1); CP_COMMIT();
        }

        __syncthreads();
        if (tid == 0) {
            __threadfence();
            unsigned a = atomicAdd(&g_bar_cnt, 1);
            if (a == 127u) {
                atomicExch(&g_bar_cnt, 0);
                __threadfence();
                atomicAdd(&g_bar_gen, 1);
            } else {
                unsigned target = bar_base + (unsigned)t + 1u;
                while ((int)(ld_acq(&g_bar_gen) - target) < 0) { }
            }
        }
        __syncthreads();
    }
}

// ---------------- conversion / small kernels --------------------------------
__global__ void conv_act(const float* __restrict__ W, __half* __restrict__ Wp, int total)
{
    int i = blockIdx.x * blockDim.x + threadIdx.x;
    if (i >= total) return;
    Wp[i] = __float2half(W[i]);
}

// single-fp16 gate-interleaved permutation: orig row q*1024+j -> j*4+q
__global__ void conv_act_perm(const float* __restrict__ W, __half* __restrict__ Wp, int total)
{
    int i = blockIdx.x * blockDim.x + threadIdx.x;
    if (i >= total) return;
    int r = i >> 10, k = i & 1023;
    int q = r >> 10, j = r & 1023;
    Wp[(size_t)(j * 4 + q) * KA + k] = __float2half(W[i]);
}

__global__ void init_misc()
{
    if (threadIdx.x == 0 && blockIdx.x == 0) {
        g_bar_cnt = 0;
        g_bar_gen = 0;
    }
}

__global__ void bias_combine_perm(const float* __restrict__ b_ih, const float* __restrict__ b_hh)
{
    int i = blockIdx.x * blockDim.x + threadIdx.x;
    if (i >= G4) return;
    int q = i >> 10, j = i & 1023;
    g_bias[j * 4 + q] = b_ih[i] + b_hh[i];
}

// softmax + 2-term fp16 split emit: g_A2[x][0:128]=hi, [128:256]=lo
__global__ void softmax128(const float* __restrict__ W)
{
    int row = blockIdx.x;
    int t = threadIdx.x;
    int lane = t & 31, warp = t >> 5;
    __shared__ float red[4];
    float v = W[row * SEQ + t];

    float m = v;
    #pragma unroll
    for (int o = 16; o > 0; o >>= 1) m = fmaxf(m, __shfl_xor_sync(0xffffffffu, m, o));
    if (lane == 0) red[warp] = m;
    __syncthreads();
    m = fmaxf(fmaxf(red[0], red[1]), fmaxf(red[2], red[3]));
    __syncthreads();

    float e = expf(v - m);
    float s = e;
    #pragma unroll
    for (int o = 16; o > 0; o >>= 1) s += __shfl_xor_sync(0xffffffffu, s, o);
    if (lane == 0) red[warp] = s;
    __syncthreads();
    s = red[0] + red[1] + red[2] + red[3];
    float a = e / s;
    g_A[row * SEQ + t] = a;
    __half hi = __float2half(a);
    float lo = a - __half2float(hi);
    g_A2[row * 256 + t]       = hi;
    g_A2[row * 256 + 128 + t] = __float2half(lo);
}

// hsT16[n][y] = fp16(hs[y][n]); grid (BH/32, SEQ/32), block (32,8)
__global__ void transpose_hs()
{
    __shared__ float tile[32][33];
    const int tx = threadIdx.x, ty = threadIdx.y;
    const int n0 = blockIdx.x * 32;
    const int y0 = blockIdx.y * 32;
    #pragma unroll
    for (int yy = ty; yy < 32; yy += 8)
        tile[yy][tx] = g_hs[(size_t)(y0 + yy) * BH + n0 + tx];
    __syncthreads();
    #pragma unroll
    for (int rr = ty; rr < 32; rr += 8)
        g_hsT[(size_t)(n0 + rr) * SEQ + y0 + tx] = __float2half(tile[tx][rr]);
}

// ---------------- launch ----------------------------------------------------
extern "C" void kernel_launch(void* const* d_in, const int* in_sizes, int n_in,
                              void* d_out, int out_size)
{
    const float* inputs = (const float*)d_in[0];
    const float* h0     = (const float*)d_in[1];
    const float* c0     = (const float*)d_in[2];
    const float* W_ih   = (const float*)d_in[3];
    const float* W_hh   = (const float*)d_in[4];
    const float* b_ih   = (const float*)d_in[5];
    const float* b_hh   = (const float*)d_in[6];
    const float* attnW  = (const float*)d_in[7];
    const float* linW   = (const float*)d_in[8];
    const float* linb   = (const float*)d_in[9];
    float* out = (float*)d_out;

    void* p;
    cudaGetSymbolAddress(&p, g_Xp);    float* Xp    = (float*)p;
    cudaGetSymbolAddress(&p, g_hs);    float* hsb   = (float*)p;
    cudaGetSymbolAddress(&p, g_bias);  float* biasc = (float*)p;
    cudaGetSymbolAddress(&p, g_Xbf);   __half* Xbf   = (__half*)p;
    cudaGetSymbolAddress(&p, g_Wihp);  __half* Wihp  = (__half*)p;
    cudaGetSymbolAddress(&p, g_Whhp);  __half* Whhp  = (__half*)p;
    cudaGetSymbolAddress(&p, g_linWp); __half* linWp = (__half*)p;
    cudaGetSymbolAddress(&p, g_hp);    __half* hp    = (__half*)p;
    cudaGetSymbolAddress(&p, g_A2);    __half* A2    = (__half*)p;
    cudaGetSymbolAddress(&p, g_hsT);   __half* hsT   = (__half*)p;

    const int SMEM_BIG  = 4 * ((128 + 128) * BK * 2);       // 65536
    const int SMEM_PERS = 4 * 24576 + 2 * 32768 + 34816;    // 198656

    cudaFuncSetAttribute((const void*)gemm_mma<128, 128, 2, 4, 1024, 1024, 1024, 0>,
                         cudaFuncAttributeMaxDynamicSharedMemorySize, SMEM_BIG);
    cudaFuncSetAttribute((const void*)gemm_mma<128, 128, 2, 4, 256, 128, 256, 1>,
                         cudaFuncAttributeMaxDynamicSharedMemorySize, SMEM_BIG);
    cudaFuncSetAttribute((const void*)lstm_persistent,
                         cudaFuncAttributeMaxDynamicSharedMemorySize, SMEM_PERS);

    conv_act<<<(SEQ * BATCH * 1024) / 256, 256>>>(inputs, Xbf, SEQ * BATCH * 1024); // 0
    conv_act_perm<<<(G4 * 1024) / 256, 256>>>(W_ih, Wihp, G4 * 1024);               // 1
    bias_combine_perm<<<(G4 + 255) / 256, 256>>>(b_ih, b_hh);                       // 2
    conv_act_perm<<<(G4 * 1024) / 256, 256>>>(W_hh, Whhp, G4 * 1024);               // 3 (canary)
    conv_act<<<(BATCH * 1024) / 256, 256>>>(h0, hp, BATCH * 1024);                  // 4

    // 5: Xp = X16 @ W_ih16^T + bias'
    gemm_mma<128, 128, 2, 4, 1024, 1024, 1024, 0>
        <<<dim3(G4 / 128, (SEQ * BATCH) / 128), 256, SMEM_BIG>>>(
        Xbf, Wihp, biasc, Xp, G4, 1);

    init_misc<<<1, 32>>>();                                                          // 6
    softmax128<<<SEQ, SEQ>>>(attnW);                                                 // 7

    // 8: persistent recurrence (pre-barrier B/Xp prefetch, tight barrier)
    lstm_persistent<<<dim3(G4 / 128, BATCH / 64), 256, SMEM_PERS>>>(
        Whhp, Xp, c0, hsb, hp);

    // 9: hs -> hsT fp16
    transpose_hs<<<dim3(BH / 32, SEQ / 32), dim3(32, 8)>>>();

    conv_act<<<(OUTD * 1024) / 256, 256>>>(linW, linWp, OUTD * 1024);                // 10

    // 11: att16[x][bh] = (A2 @ hsT^T) via 2-term fp16 HMMA, fp16 out into Xbf
    gemm_mma<128, 128, 2, 4, 256, 128, 256, 1>
        <<<dim3(BH / 128, 1), 256, SMEM_BIG>>>(
        A2, hsT, nullptr, Xbf, BH, 0);

    // 12: out = att16 @ linW16^T + linb
    gemm_mma<128, 128, 2, 4, 1024, 1024, 1024, 0>
        <<<dim3(OUTD / 128, (SEQ * BATCH) / 128), 256, SMEM_BIG>>>(
        Xbf, linWp, linb, out, OUTD, 1);
}

// round 15
// speedup vs baseline: 2.5448x; 1.0318x over previous
#include <cuda_runtime.h>
#include <cuda_fp16.h>
#include <math.h>
#include <stdint.h>

// Problem dims
#define SEQ   128
#define BATCH 256
#define IND   1024
#define HID   1024
#define OUTD  1024
#define G4    4096
#define BH    (BATCH*HID)
#define KA    1024            // activations AND weights: fp16, rounded once
#define BK    32

// ---------------- scratch (device globals) ---------------------------------
__device__ __half g_Xp16[(size_t)SEQ * BATCH * G4];   // 256 MB (gate-interleaved, +bias)
__device__ __half g_hs16[(size_t)SEQ * BH];           // 64 MB: h fp16, [t][b][j]
__device__ float g_A[SEQ * SEQ];
__device__ float g_bias[G4];                          // gate-interleaved
__device__ __half g_Xbf[(size_t)SEQ * BATCH * KA];    // 64 MB: X16 then att16
__device__ __half g_Wihp[(size_t)G4 * KA];            // 8 MB
__device__ __half g_Whhp[(size_t)G4 * KA];            // 8 MB
__device__ __half g_linWp[(size_t)OUTD * KA];         // 2 MB
__device__ __half g_h0[(size_t)BATCH * KA];           // h0 fp16
__device__ __half g_A2[SEQ * 2 * SEQ];                // softmax(A) 2-term fp16 [hi|lo]
__device__ __half g_hsT[(size_t)BH * SEQ];            // 64 MB: hs transposed fp16 [n][y]
__device__ unsigned g_bar_cnt;
__device__ unsigned g_bar_gen;

// ---------------- PTX helpers ----------------------------------------------
__device__ __forceinline__ uint32_t smem_u32(const void* p) {
    uint32_t a;
    asm("{ .reg .u64 t; cvta.to.shared.u64 t, %1; cvt.u32.u64 %0, t; }"
        : "=r"(a) : "l"(p));
    return a;
}

#define CP_ASYNC16(dst, src) \
    asm volatile("cp.async.cg.shared.global [%0], [%1], 16;" :: "r"(dst), "l"(src))
#define CP_COMMIT()  asm volatile("cp.async.commit_group;" ::: "memory")
#define CP_WAIT2()   asm volatile("cp.async.wait_group 2;" ::: "memory")
#define CP_WAIT1()   asm volatile("cp.async.wait_group 1;" ::: "memory")
#define CP_WAIT0()   asm volatile("cp.async.wait_group 0;" ::: "memory")

#define LDMX4(r0, r1, r2, r3, addr) \
    asm volatile("ldmatrix.sync.aligned.m8n8.x4.shared.b16 {%0,%1,%2,%3}, [%4];" \
                 : "=r"(r0), "=r"(r1), "=r"(r2), "=r"(r3) : "r"(addr))

#define MMA16816(d, a, b) \
    asm volatile("mma.sync.aligned.m16n8k16.row.col.f32.f16.f16.f32 " \
                 "{%0,%1,%2,%3}, {%4,%5,%6,%7}, {%8,%9}, {%0,%1,%2,%3};" \
                 : "+f"((d)[0]), "+f"((d)[1]), "+f"((d)[2]), "+f"((d)[3]) \
                 : "r"((a)[0]), "r"((a)[1]), "r"((a)[2]), "r"((a)[3]), \
                   "r"((b)[0]), "r"((b)[1]))

// swizzled 16B-chunk byte offset, 64B rows (4 chunks of 8 fp16)
__device__ __forceinline__ uint32_t swz(int row, int c) {
    return (uint32_t)((row * 4 + (c ^ ((row >> 1) & 3))) * 16);
}

// swizzled 16B-chunk byte offset, 128B rows (8 chunks) — recurrence BK=64
__device__ __forceinline__ uint32_t swz64(int row, int c) {
    return (uint32_t)((row * 8 + (c ^ (row & 7))) * 16);
}

__device__ __forceinline__ float sigmf(float x) {
    return 1.0f / (1.0f + __expf(-x));
}

__device__ __forceinline__ unsigned ld_acq(unsigned* p) {
    unsigned v;
    asm volatile("ld.acquire.gpu.global.u32 %0, [%1];" : "=r"(v) : "l"(p) : "memory");
    return v;
}

// ---------------- fp16 HMMA GEMM (generalized) ------------------------------
// C[M,N] = A16[M,KAW-wrapped] @ B16[N,KBW-wrapped]^T (+bias), fp32 accum over
// KIT. HOUT: write fp16. 256 threads = 8 warps. BK=32, 4-stage cp.async.
template<int BM, int BN, int WGM, int WGN, int KAW, int KBW, int KIT, int HOUT>
__global__ __launch_bounds__(256)
void gemm_mma(const __half* __restrict__ A,
              const __half* __restrict__ B,
              const float* __restrict__ bias,
              void* __restrict__ Cv,
              int N, int hasBias)
{
    constexpr int NCC = KIT / BK;
    constexpr int WM = BM / WGM;
    constexpr int WN = BN / WGN;
    constexpr int MA = WM / 16;
    constexpr int NA = WN / 8;
    constexpr int A_BYTES = BM * BK * 2;
    constexpr int B_BYTES = BN * BK * 2;
    constexpr int STAGE   = A_BYTES + B_BYTES;

    extern __shared__ __align__(128) char smem[];
    const uint32_t sb = smem_u32(smem);

    const int tid = threadIdx.x;
    const int wid = tid >> 5;
    const int lid = tid & 31;
    const int g   = lid >> 2;
    const int tg  = lid & 3;
    const int wm  = wid / WGN;
    const int wn  = wid % WGN;
    const int bm0 = blockIdx.y * BM;
    const int bn0 = blockIdx.x * BN;

    float acc[MA][NA][4];
    #pragma unroll
    for (int i = 0; i < MA; ++i)
        #pragma unroll
        for (int j = 0; j < NA; ++j)
            #pragma unroll
            for (int q = 0; q < 4; ++q) acc[i][j][q] = 0.f;

    auto load_tile = [&](int c, int s) {
        const uint32_t abase = sb + s * STAGE;
        const uint32_t bbase = abase + A_BYTES;
        const int ka0 = (c & (KAW / BK - 1)) * BK;
        const int kb0 = (c & (KBW / BK - 1)) * BK;
        #pragma unroll
        for (int u = tid; u < BM * 4; u += 256) {
            int r = u >> 2, cc = u & 3;
            CP_ASYNC16(abase + swz(r, cc),
                       A + (size_t)(bm0 + r) * KAW + ka0 + cc * 8);
        }
        #pragma unroll
        for (int u = tid; u < BN * 4; u += 256) {
            int r = u >> 2, cc = u & 3;
            CP_ASYNC16(bbase + swz(r, cc),
                       B + (size_t)(bn0 + r) * KBW + kb0 + cc * 8);
        }
    };

    load_tile(0, 0); CP_COMMIT();
    load_tile(1, 1); CP_COMMIT();
    load_tile(2, 2); CP_COMMIT();

    for (int c = 0; c < NCC; ++c) {
        if (c <= NCC - 3)      { CP_WAIT2(); }
        else if (c == NCC - 2) { CP_WAIT1(); }
        else                   { CP_WAIT0(); }
        __syncthreads();
        if (c + 3 < NCC) { load_tile(c + 3, (c + 3) & 3); CP_COMMIT(); }

        const uint32_t abase = sb + (c & 3) * STAGE;
        const uint32_t bbase = abase + A_BYTES;

        #pragma unroll
        for (int ks = 0; ks < 2; ++ks) {
            uint32_t afr[MA][4];
            #pragma unroll
            for (int ma = 0; ma < MA; ++ma) {
                int row = wm * WM + ma * 16 + (lid & 15);
                int cc  = 2 * ks + (lid >> 4);
                LDMX4(afr[ma][0], afr[ma][1], afr[ma][2], afr[ma][3],
                      abase + swz(row, cc));
            }
            uint32_t bfr[NA][2];
            #pragma unroll
            for (int np = 0; np < NA / 2; ++np) {
                int row = wn * WN + np * 16 + (lid & 15);
                int cc  = 2 * ks + (lid >> 4);
                uint32_t r0, r1, r2, r3;
                LDMX4(r0, r1, r2, r3, bbase + swz(row, cc));
                bfr[2 * np + 0][0] = r0; bfr[2 * np + 1][0] = r1;
                bfr[2 * np + 0][1] = r2; bfr[2 * np + 1][1] = r3;
            }
            #pragma unroll
            for (int ma = 0; ma < MA; ++ma)
                #pragma unroll
                for (int na = 0; na < NA; ++na)
                    MMA16816(acc[ma][na], afr[ma], bfr[na]);
        }
    }

    #pragma unroll
    for (int ma = 0; ma < MA; ++ma) {
        #pragma unroll
        for (int na = 0; na < NA; ++na) {
            const int col = bn0 + wn * WN + na * 8 + tg * 2;
            const int r0  = bm0 + wm * WM + ma * 16 + g;
            const int r1  = r0 + 8;
            float2 v0 = make_float2(acc[ma][na][0], acc[ma][na][1]);
            float2 v1 = make_float2(acc[ma][na][2], acc[ma][na][3]);
            if (hasBias) {
                float2 bv = *reinterpret_cast<const float2*>(bias + col);
                v0.x += bv.x; v0.y += bv.y; v1.x += bv.x; v1.y += bv.y;
            }
            if constexpr (HOUT) {
                __half* C16 = (__half*)Cv;
                *reinterpret_cast<__half2*>(C16 + (size_t)r0 * N + col) =
                    __floats2half2_rn(v0.x, v0.y);
                *reinterpret_cast<__half2*>(C16 + (size_t)r1 * N + col) =
                    __floats2half2_rn(v1.x, v1.y);
            } else {
                float* C = (float*)Cv;
                *reinterpret_cast<float2*>(C + (size_t)r0 * N + col) = v0;
                *reinterpret_cast<float2*>(C + (size_t)r1 * N + col) = v1;
            }
        }
    }
}

// ---------------- persistent LSTM recurrence (BK=64, K=1024) ----------------
// 128 CTAs (grid 32x4). Xp is fp16 (bias folded). h stored fp16 once into
// hs16[t]; next step reads hs16[t-1] directly (no separate h' buffer).
// Weight chunks 0-2 + Xp(t+1) prefetched PRE-barrier.
__global__ __launch_bounds__(256)
void lstm_persistent(const __half* __restrict__ Whhp,
                     const __half* __restrict__ Xp16,
                     const float* __restrict__ c0,
                     __half* __restrict__ hs16,
                     const __half* __restrict__ h016)
{
    constexpr int BKR = 64;
    constexpr int NC  = KA / BKR;               // 16 chunks
    constexpr int BM = 64, BN = 128, WGN = 4;
    constexpr int WM = 32, WN = 32, MA = 2, NA = 4;
    constexpr int A_BYTES = BM * BKR * 2;       // 8192
    constexpr int B_BYTES = BN * BKR * 2;       // 16384
    constexpr int STG     = A_BYTES + B_BYTES;  // 24576
    constexpr int XP_OFF  = 4 * STG;            // 98304, two 16KB buffers
    constexpr int XPBUF   = BM * BN * 2;        // 16384
    constexpr int ST_OFF  = XP_OFF + 2 * XPBUF; // 131072
    constexpr int BNP     = BN + 4;

    extern __shared__ __align__(128) char smem[];
    const uint32_t sb = smem_u32(smem);
    float* st = reinterpret_cast<float*>(smem + ST_OFF);

    const int tid = threadIdx.x;
    const int wid = tid >> 5;
    const int lid = tid & 31;
    const int wm  = wid / WGN;
    const int wn  = wid % WGN;
    const int bn0 = blockIdx.x * BN;
    const int bm0 = blockIdx.y * BM;
    const int j0  = bn0 >> 2;

    float c_reg[8];
    #pragma unroll
    for (int k = 0; k < 8; ++k) {
        int idx = tid + 256 * k;
        int r = idx >> 5, jj = idx & 31;
        c_reg[k] = c0[(bm0 + r) * HID + j0 + jj];
    }

    auto loadA = [&](const __half* Ap, int c, int s) {
        const uint32_t ab = sb + s * STG;
        const int k0 = c * BKR;
        #pragma unroll
        for (int it = 0; it < 2; ++it) {   // 64 rows x 8 chunks = 512
            int u = tid + it * 256;
            int r = u >> 3, cc = u & 7;
            CP_ASYNC16(ab + swz64(r, cc),
                       Ap + (size_t)(bm0 + r) * KA + k0 + cc * 8);
        }
    };
    auto loadB = [&](int c, int s) {
        const uint32_t bb = sb + s * STG + A_BYTES;
        const int k0 = c * BKR;
        #pragma unroll
        for (int it = 0; it < 4; ++it) {   // 128 rows x 8 chunks = 1024
            int u = tid + it * 256;
            int r = u >> 3, cc = u & 7;
            CP_ASYNC16(bb + swz64(r, cc),
                       Whhp + (size_t)(bn0 + r) * KA + k0 + cc * 8);
        }
    };
    auto loadXp = [&](int t, int buf) {
        // tile [64 rows][128 fp16] = 1024 16B-chunks (16 per row)
        const __half* xsrc = Xp16 + ((size_t)t * BATCH + bm0) * G4 + bn0;
        #pragma unroll
        for (int k = 0; k < 4; ++k) {
            int idx = tid + 256 * k;
            int r = idx >> 4, q = idx & 15;
            CP_ASYNC16(sb + XP_OFF + (uint32_t)buf * XPBUF + (uint32_t)idx * 16,
                       xsrc + (size_t)r * G4 + q * 8);
        }
    };

    unsigned bar_base = 0;
    if (tid == 0) bar_base = ld_acq(&g_bar_gen);

    // pre-loop "pre-barrier" block for t=0
    loadB(0, 0); CP_COMMIT();
    loadB(1, 1); CP_COMMIT();
    loadB(2, 2); loadXp(0, 0); CP_COMMIT();

    for (int t = 0; t < SEQ; ++t) {
        const __half* Ap = (t == 0) ? h016 : hs16 + (size_t)(t - 1) * BH;
        const __half* xp_s = reinterpret_cast<const __half*>(
            smem + XP_OFF + (t & 1) * XPBUF);

        // post-barrier A loads (depend on h_t)
        loadA(Ap, 0, 0); CP_COMMIT();
        loadA(Ap, 1, 1); CP_COMMIT();
        loadA(Ap, 2, 2); CP_COMMIT();

        float acc[MA][NA][4];
        #pragma unroll
        for (int i = 0; i < MA; ++i)
            #pragma unroll
            for (int j = 0; j < NA; ++j)
                #pragma unroll
                for (int q = 0; q < 4; ++q) acc[i][j][q] = 0.f;

        for (int c = 0; c < NC; ++c) {
            if (c <= NC - 3)      { CP_WAIT2(); }
            else if (c == NC - 2) { CP_WAIT1(); }
            else                  { CP_WAIT0(); }
            __syncthreads();
            if (c + 3 < NC) {
                loadA(Ap, c + 3, (c + 3) & 3);
                loadB(c + 3, (c + 3) & 3);
                CP_COMMIT();
            }

            const uint32_t ab = sb + (c & 3) * STG;
            const uint32_t bb = ab + A_BYTES;
            #pragma unroll
            for (int ks = 0; ks < 4; ++ks) {
                uint32_t afr[MA][4];
                #pragma unroll
                for (int ma = 0; ma < MA; ++ma) {
                    int row = wm * WM + ma * 16 + (lid & 15);
                    int cc  = 2 * ks + (lid >> 4);
                    LDMX4(afr[ma][0], afr[ma][1], afr[ma][2], afr[ma][3],
                          ab + swz64(row, cc));
                }
                uint32_t bfr[NA][2];
                #pragma unroll
                for (int np = 0; np < NA / 2; ++np) {
                    int row = wn * WN + np * 16 + (lid & 15);
                    int cc  = 2 * ks + (lid >> 4);
                    uint32_t r0, r1, r2, r3;
                    LDMX4(r0, r1, r2, r3, bb + swz64(row, cc));
                    bfr[2 * np + 0][0] = r0; bfr[2 * np + 1][0] = r1;
                    bfr[2 * np + 0][1] = r2; bfr[2 * np + 1][1] = r3;
                }
                #pragma unroll
                for (int ma = 0; ma < MA; ++ma)
                    #pragma unroll
                    for (int na = 0; na < NA; ++na)
                        MMA16816(acc[ma][na], afr[ma], bfr[na]);
            }
        }

        const int g  = lid >> 2;
        const int tg = lid & 3;
        #pragma unroll
        for (int ma = 0; ma < MA; ++ma) {
            #pragma unroll
            for (int na = 0; na < NA; ++na) {
                const int col = wn * WN + na * 8 + tg * 2;
                const int r0  = wm * WM + ma * 16 + g;
                const int r1  = r0 + 8;
                st[r0 * BNP + col]     = acc[ma][na][0];
                st[r0 * BNP + col + 1] = acc[ma][na][1];
                st[r1 * BNP + col]     = acc[ma][na][2];
                st[r1 * BNP + col + 1] = acc[ma][na][3];
            }
        }
        __syncthreads();

        __half* hsrow = hs16 + (size_t)t * BH;
        #pragma unroll
        for (int k = 0; k < 8; ++k) {
            int idx = tid + 256 * k;
            int r = idx >> 5, jj = idx & 31;
            float4 gq = *reinterpret_cast<const float4*>(st + r * BNP + 4 * jj);
            // 4 fp16 Xp values for this quad
            uint2 xr = *reinterpret_cast<const uint2*>(
                reinterpret_cast<const char*>(xp_s) + (r * BN + 4 * jj) * 2);
            float2 x01 = __half22float2(*reinterpret_cast<const __half2*>(&xr.x));
            float2 x23 = __half22float2(*reinterpret_cast<const __half2*>(&xr.y));
            float gi = sigmf(gq.x + x01.x);
            float gf = sigmf(gq.y + x01.y);
            float gg = tanhf(gq.z + x23.x);
            float go = sigmf(gq.w + x23.y);
            float cv = gf * c_reg[k] + gi * gg;
            c_reg[k] = cv;
            float h = go * tanhf(cv);
            int b = bm0 + r;
            hsrow[b * HID + j0 + jj] = __float2half(h);
        }

        // pre-barrier prefetch for step t+1 (no h dependence)
        if (t + 1 < SEQ) {
            loadB(0, 0); CP_COMMIT();
            loadB(1, 1); CP_COMMIT();
            loadB(2, 2); loadXp(t + 1, (t + 1) & 1); CP_COMMIT();
        }

        __syncthreads();
        if (tid == 0) {
            __threadfence();
            unsigned a = atomicAdd(&g_bar_cnt, 1);
            if (a == 127u) {
                atomicExch(&g_bar_cnt, 0);
                __threadfence();
                atomicAdd(&g_bar_gen, 1);
            } else {
                unsigned target = bar_base + (unsigned)t + 1u;
                while ((int)(ld_acq(&g_bar_gen) - target) < 0) { }
            }
        }
        __syncthreads();
    }
}

// ---------------- conversion / small kernels --------------------------------
__global__ void conv_act(const float* __restrict__ W, __half* __restrict__ Wp, int total)
{
    int i = blockIdx.x * blockDim.x + threadIdx.x;
    if (i >= total) return;
    Wp[i] = __float2half(W[i]);
}

// single-fp16 gate-interleaved permutation: orig row q*1024+j -> j*4+q
__global__ void conv_act_perm(const float* __restrict__ W, __half* __restrict__ Wp, int total)
{
    int i = blockIdx.x * blockDim.x + threadIdx.x;
    if (i >= total) return;
    int r = i >> 10, k = i & 1023;
    int q = r >> 10, j = r & 1023;
    Wp[(size_t)(j * 4 + q) * KA + k] = __float2half(W[i]);
}

__global__ void init_misc()
{
    if (threadIdx.x == 0 && blockIdx.x == 0) {
        g_bar_cnt = 0;
        g_bar_gen = 0;
    }
}

__global__ void bias_combine_perm(const float* __restrict__ b_ih, const float* __restrict__ b_hh)
{
    int i = blockIdx.x * blockDim.x + threadIdx.x;
    if (i >= G4) return;
    int q = i >> 10, j = i & 1023;
    g_bias[j * 4 + q] = b_ih[i] + b_hh[i];
}

// softmax + 2-term fp16 split emit: g_A2[x][0:128]=hi, [128:256]=lo
__global__ void softmax128(const float* __restrict__ W)
{
    int row = blockIdx.x;
    int t = threadIdx.x;
    int lane = t & 31, warp = t >> 5;
    __shared__ float red[4];
    float v = W[row * SEQ + t];

    float m = v;
    #pragma unroll
    for (int o = 16; o > 0; o >>= 1) m = fmaxf(m, __shfl_xor_sync(0xffffffffu, m, o));
    if (lane == 0) red[warp] = m;
    __syncthreads();
    m = fmaxf(fmaxf(red[0], red[1]), fmaxf(red[2], red[3]));
    __syncthreads();

    float e = expf(v - m);
    float s = e;
    #pragma unroll
    for (int o = 16; o > 0; o >>= 1) s += __shfl_xor_sync(0xffffffffu, s, o);
    if (lane == 0) red[warp] = s;
    __syncthreads();
    s = red[0] + red[1] + red[2] + red[3];
    float a = e / s;
    g_A[row * SEQ + t] = a;
    __half hi = __float2half(a);
    float lo = a - __half2float(hi);
    g_A2[row * 256 + t]       = hi;
    g_A2[row * 256 + 128 + t] = __float2half(lo);
}

// hsT16[n][y] = hs16[y][n]; grid (BH/32, SEQ/32), block (32,8)
__global__ void transpose_hs()
{
    __shared__ __half tile[32][34];
    const int tx = threadIdx.x, ty = threadIdx.y;
    const int n0 = blockIdx.x * 32;
    const int y0 = blockIdx.y * 32;
    #pragma unroll
    for (int yy = ty; yy < 32; yy += 8)
        tile[yy][tx] = g_hs16[(size_t)(y0 + yy) * BH + n0 + tx];
    __syncthreads();
    #pragma unroll
    for (int rr = ty; rr < 32; rr += 8)
        g_hsT[(size_t)(n0 + rr) * SEQ + y0 + tx] = tile[tx][rr];
}

// ---------------- launch ----------------------------------------------------
extern "C" void kernel_launch(void* const* d_in, const int* in_sizes, int n_in,
                              void* d_out, int out_size)
{
    const float* inputs = (const float*)d_in[0];
    const float* h0     = (const float*)d_in[1];
    const float* c0     = (const float*)d_in[2];
    const float* W_ih   = (const float*)d_in[3];
    const float* W_hh   = (const float*)d_in[4];
    const float* b_ih   = (const float*)d_in[5];
    const float* b_hh   = (const float*)d_in[6];
    const float* attnW  = (const float*)d_in[7];
    const float* linW   = (const float*)d_in[8];
    const float* linb   = (const float*)d_in[9];
    float* out = (float*)d_out;

    void* p;
    cudaGetSymbolAddress(&p, g_Xp16);  __half* Xp16  = (__half*)p;
    cudaGetSymbolAddress(&p, g_hs16);  __half* hs16  = (__half*)p;
    cudaGetSymbolAddress(&p, g_bias);  float* biasc = (float*)p;
    cudaGetSymbolAddress(&p, g_Xbf);   __half* Xbf   = (__half*)p;
    cudaGetSymbolAddress(&p, g_Wihp);  __half* Wihp  = (__half*)p;
    cudaGetSymbolAddress(&p, g_Whhp);  __half* Whhp  = (__half*)p;
    cudaGetSymbolAddress(&p, g_linWp); __half* linWp = (__half*)p;
    cudaGetSymbolAddress(&p, g_h0);    __half* h016  = (__half*)p;
    cudaGetSymbolAddress(&p, g_A2);    __half* A2    = (__half*)p;
    cudaGetSymbolAddress(&p, g_hsT);   __half* hsT   = (__half*)p;

    const int SMEM_BIG  = 4 * ((128 + 128) * BK * 2);            // 65536
    const int SMEM_PERS = 4 * 24576 + 2 * 16384 + 34816;         // 165888

    cudaFuncSetAttribute((const void*)gemm_mma<128, 128, 2, 4, 1024, 1024, 1024, 0>,
                         cudaFuncAttributeMaxDynamicSharedMemorySize, SMEM_BIG);
    cudaFuncSetAttribute((const void*)gemm_mma<128, 128, 2, 4, 1024, 1024, 1024, 1>,
                         cudaFuncAttributeMaxDynamicSharedMemorySize, SMEM_BIG);
    cudaFuncSetAttribute((const void*)gemm_mma<128, 128, 2, 4, 256, 128, 256, 1>,
                         cudaFuncAttributeMaxDynamicSharedMemorySize, SMEM_BIG);
    cudaFuncSetAttribute((const void*)lstm_persistent,
                         cudaFuncAttributeMaxDynamicSharedMemorySize, SMEM_PERS);

    conv_act<<<(SEQ * BATCH * 1024) / 256, 256>>>(inputs, Xbf, SEQ * BATCH * 1024); // 0
    conv_act_perm<<<(G4 * 1024) / 256, 256>>>(W_ih, Wihp, G4 * 1024);               // 1
    bias_combine_perm<<<(G4 + 255) / 256, 256>>>(b_ih, b_hh);                       // 2
    conv_act_perm<<<(G4 * 1024) / 256, 256>>>(W_hh, Whhp, G4 * 1024);               // 3 (canary)
    conv_act<<<(BATCH * 1024) / 256, 256>>>(h0, h016, BATCH * 1024);                // 4

    // 5: Xp16 = fp16(X16 @ W_ih16^T + bias')
    gemm_mma<128, 128, 2, 4, 1024, 1024, 1024, 1>
        <<<dim3(G4 / 128, (SEQ * BATCH) / 128), 256, SMEM_BIG>>>(
        Xbf, Wihp, biasc, Xp16, G4, 1);

    init_misc<<<1, 32>>>();                                                          // 6
    softmax128<<<SEQ, SEQ>>>(attnW);                                                 // 7

    // 8: persistent recurrence (fp16 Xp, h stored once as fp16 into hs16)
    lstm_persistent<<<dim3(G4 / 128, BATCH / 64), 256, SMEM_PERS>>>(
        Whhp, Xp16, c0, hs16, h016);

    // 9: hs16 -> hsT
    transpose_hs<<<dim3(BH / 32, SEQ / 32), dim3(32, 8)>>>();

    conv_act<<<(OUTD * 1024) / 256, 256>>>(linW, linWp, OUTD * 1024);                // 10

    // 11: att16 = (A2 @ hsT^T) via 2-term fp16 HMMA, fp16 out into Xbf
    gemm_mma<128, 128, 2, 4, 256, 128, 256, 1>
        <<<dim3(BH / 128, 1), 256, SMEM_BIG>>>(
        A2, hsT, nullptr, Xbf, BH, 0);

    // 12: out = att16 @ linW16^T + linb
    gemm_mma<128, 128, 2, 4, 1024, 1024, 1024, 0>
        <<<dim3(OUTD / 128, (SEQ * BATCH) / 128), 256, SMEM_BIG>>>(
        Xbf, linWp, linb, out, OUTD, 1);
}

// round 17
// speedup vs baseline: 2.6224x; 1.0305x over previous
#include <cuda_runtime.h>
#include <cuda_fp16.h>
#include <math.h>
#include <stdint.h>

// Problem dims
#define SEQ   128
#define BATCH 256
#define IND   1024
#define HID   1024
#define OUTD  1024
#define G4    4096
#define BH    (BATCH*HID)
#define KA    1024            // activations AND weights: fp16, rounded once
#define BK    32

// ---------------- scratch (device globals) ---------------------------------
__device__ __half g_Xp16[(size_t)SEQ * BATCH * G4];   // 256 MB (gate-interleaved, +bias)
__device__ __half g_hs16[(size_t)SEQ * BH];           // 64 MB: h fp16, [t][b][j]
__device__ float g_bias[G4];                          // gate-interleaved
__device__ __half g_Xbf[(size_t)SEQ * BATCH * KA];    // 64 MB: X16 then att16
__device__ __half g_Wihp[(size_t)G4 * KA];            // 8 MB
__device__ __half g_Whhp[(size_t)G4 * KA];            // 8 MB
__device__ __half g_linWp[(size_t)OUTD * KA];         // 2 MB
__device__ __half g_h0[(size_t)BATCH * KA];           // h0 fp16
__device__ __half g_A2[SEQ * 2 * SEQ];                // softmax(A) 2-term fp16 [hi|lo]
__device__ __half g_hsT[(size_t)BH * SEQ];            // 64 MB: hs transposed fp16 [n][y]
__device__ unsigned g_bar_cnt[4];
__device__ unsigned g_bar_gen[4];

// ---------------- PTX helpers ----------------------------------------------
__device__ __forceinline__ uint32_t smem_u32(const void* p) {
    uint32_t a;
    asm("{ .reg .u64 t; cvta.to.shared.u64 t, %1; cvt.u32.u64 %0, t; }"
        : "=r"(a) : "l"(p));
    return a;
}

#define CP_ASYNC16(dst, src) \
    asm volatile("cp.async.cg.shared.global [%0], [%1], 16;" :: "r"(dst), "l"(src))
#define CP_COMMIT()  asm volatile("cp.async.commit_group;" ::: "memory")
#define CP_WAIT2()   asm volatile("cp.async.wait_group 2;" ::: "memory")
#define CP_WAIT1()   asm volatile("cp.async.wait_group 1;" ::: "memory")
#define CP_WAIT0()   asm volatile("cp.async.wait_group 0;" ::: "memory")

#define LDMX4(r0, r1, r2, r3, addr) \
    asm volatile("ldmatrix.sync.aligned.m8n8.x4.shared.b16 {%0,%1,%2,%3}, [%4];" \
                 : "=r"(r0), "=r"(r1), "=r"(r2), "=r"(r3) : "r"(addr))

#define MMA16816(d, a, b) \
    asm volatile("mma.sync.aligned.m16n8k16.row.col.f32.f16.f16.f32 " \
                 "{%0,%1,%2,%3}, {%4,%5,%6,%7}, {%8,%9}, {%0,%1,%2,%3};" \
                 : "+f"((d)[0]), "+f"((d)[1]), "+f"((d)[2]), "+f"((d)[3]) \
                 : "r"((a)[0]), "r"((a)[1]), "r"((a)[2]), "r"((a)[3]), \
                   "r"((b)[0]), "r"((b)[1]))

// swizzled 16B-chunk byte offset, 64B rows (4 chunks of 8 fp16)
__device__ __forceinline__ uint32_t swz(int row, int c) {
    return (uint32_t)((row * 4 + (c ^ ((row >> 1) & 3))) * 16);
}

// swizzled 16B-chunk byte offset, 128B rows (8 chunks) — recurrence BK=64
__device__ __forceinline__ uint32_t swz64(int row, int c) {
    return (uint32_t)((row * 8 + (c ^ (row & 7))) * 16);
}

__device__ __forceinline__ float sigmf(float x) {
    return 1.0f / (1.0f + __expf(-x));
}

__device__ __forceinline__ unsigned ld_acq(unsigned* p) {
    unsigned v;
    asm volatile("ld.acquire.gpu.global.u32 %0, [%1];" : "=r"(v) : "l"(p) : "memory");
    return v;
}

// ---------------- fp16 HMMA GEMM (generalized) ------------------------------
// C[M,N] = A16[M,KAW-wrapped] @ B16[N,KBW-wrapped]^T (+bias), fp32 accum over
// KIT. HOUT: write fp16. 256 threads = 8 warps. BK=32, 4-stage cp.async.
template<int BM, int BN, int WGM, int WGN, int KAW, int KBW, int KIT, int HOUT>
__global__ __launch_bounds__(256)
void gemm_mma(const __half* __restrict__ A,
              const __half* __restrict__ B,
              const float* __restrict__ bias,
              void* __restrict__ Cv,
              int N, int hasBias)
{
    constexpr int NCC = KIT / BK;
    constexpr int WM = BM / WGM;
    constexpr int WN = BN / WGN;
    constexpr int MA = WM / 16;
    constexpr int NA = WN / 8;
    constexpr int A_BYTES = BM * BK * 2;
    constexpr int B_BYTES = BN * BK * 2;
    constexpr int STAGE   = A_BYTES + B_BYTES;

    extern __shared__ __align__(128) char smem[];
    const uint32_t sb = smem_u32(smem);

    const int tid = threadIdx.x;
    const int wid = tid >> 5;
    const int lid = tid & 31;
    const int g   = lid >> 2;
    const int tg  = lid & 3;
    const int wm  = wid / WGN;
    const int wn  = wid % WGN;
    const int bm0 = blockIdx.y * BM;
    const int bn0 = blockIdx.x * BN;

    float acc[MA][NA][4];
    #pragma unroll
    for (int i = 0; i < MA; ++i)
        #pragma unroll
        for (int j = 0; j < NA; ++j)
            #pragma unroll
            for (int q = 0; q < 4; ++q) acc[i][j][q] = 0.f;

    auto load_tile = [&](int c, int s) {
        const uint32_t abase = sb + s * STAGE;
        const uint32_t bbase = abase + A_BYTES;
        const int ka0 = (c & (KAW / BK - 1)) * BK;
        const int kb0 = (c & (KBW / BK - 1)) * BK;
        #pragma unroll
        for (int u = tid; u < BM * 4; u += 256) {
            int r = u >> 2, cc = u & 3;
            CP_ASYNC16(abase + swz(r, cc),
                       A + (size_t)(bm0 + r) * KAW + ka0 + cc * 8);
        }
        #pragma unroll
        for (int u = tid; u < BN * 4; u += 256) {
            int r = u >> 2, cc = u & 3;
            CP_ASYNC16(bbase + swz(r, cc),
                       B + (size_t)(bn0 + r) * KBW + kb0 + cc * 8);
        }
    };

    load_tile(0, 0); CP_COMMIT();
    load_tile(1, 1); CP_COMMIT();
    load_tile(2, 2); CP_COMMIT();

    for (int c = 0; c < NCC; ++c) {
        if (c <= NCC - 3)      { CP_WAIT2(); }
        else if (c == NCC - 2) { CP_WAIT1(); }
        else                   { CP_WAIT0(); }
        __syncthreads();
        if (c + 3 < NCC) { load_tile(c + 3, (c + 3) & 3); CP_COMMIT(); }

        const uint32_t abase = sb + (c & 3) * STAGE;
        const uint32_t bbase = abase + A_BYTES;

        #pragma unroll
        for (int ks = 0; ks < 2; ++ks) {
            uint32_t afr[MA][4];
            #pragma unroll
            for (int ma = 0; ma < MA; ++ma) {
                int row = wm * WM + ma * 16 + (lid & 15);
                int cc  = 2 * ks + (lid >> 4);
                LDMX4(afr[ma][0], afr[ma][1], afr[ma][2], afr[ma][3],
                      abase + swz(row, cc));
            }
            uint32_t bfr[NA][2];
            #pragma unroll
            for (int np = 0; np < NA / 2; ++np) {
                int row = wn * WN + np * 16 + (lid & 15);
                int cc  = 2 * ks + (lid >> 4);
                uint32_t r0, r1, r2, r3;
                LDMX4(r0, r1, r2, r3, bbase + swz(row, cc));
                bfr[2 * np + 0][0] = r0; bfr[2 * np + 1][0] = r1;
                bfr[2 * np + 0][1] = r2; bfr[2 * np + 1][1] = r3;
            }
            #pragma unroll
            for (int ma = 0; ma < MA; ++ma)
                #pragma unroll
                for (int na = 0; na < NA; ++na)
                    MMA16816(acc[ma][na], afr[ma], bfr[na]);
        }
    }

    #pragma unroll
    for (int ma = 0; ma < MA; ++ma) {
        #pragma unroll
        for (int na = 0; na < NA; ++na) {
            const int col = bn0 + wn * WN + na * 8 + tg * 2;
            const int r0  = bm0 + wm * WM + ma * 16 + g;
            const int r1  = r0 + 8;
            float2 v0 = make_float2(acc[ma][na][0], acc[ma][na][1]);
            float2 v1 = make_float2(acc[ma][na][2], acc[ma][na][3]);
            if (hasBias) {
                float2 bv = *reinterpret_cast<const float2*>(bias + col);
                v0.x += bv.x; v0.y += bv.y; v1.x += bv.x; v1.y += bv.y;
            }
            if constexpr (HOUT) {
                __half* C16 = (__half*)Cv;
                *reinterpret_cast<__half2*>(C16 + (size_t)r0 * N + col) =
                    __floats2half2_rn(v0.x, v0.y);
                *reinterpret_cast<__half2*>(C16 + (size_t)r1 * N + col) =
                    __floats2half2_rn(v1.x, v1.y);
            } else {
                float* C = (float*)Cv;
                *reinterpret_cast<float2*>(C + (size_t)r0 * N + col) = v0;
                *reinterpret_cast<float2*>(C + (size_t)r1 * N + col) = v1;
            }
        }
    }
}

// ---------------- persistent LSTM recurrence (BK=64, K=1024) ----------------
// 128 CTAs (grid 32x4). Per-row-group barriers: CTA (bn,bm) only depends on
// the 32 CTAs sharing its bm group (they write h rows [bm0,bm0+64)).
__global__ __launch_bounds__(256)
void lstm_persistent(const __half* __restrict__ Whhp,
                     const __half* __restrict__ Xp16,
                     const float* __restrict__ c0,
                     __half* __restrict__ hs16,
                     const __half* __restrict__ h016)
{
    constexpr int BKR = 64;
    constexpr int NC  = KA / BKR;               // 16 chunks
    constexpr int BM = 64, BN = 128, WGN = 4;
    constexpr int WM = 32, WN = 32, MA = 2, NA = 4;
    constexpr int A_BYTES = BM * BKR * 2;       // 8192
    constexpr int B_BYTES = BN * BKR * 2;       // 16384
    constexpr int STG     = A_BYTES + B_BYTES;  // 24576
    constexpr int XP_OFF  = 4 * STG;            // 98304, two 16KB buffers
    constexpr int XPBUF   = BM * BN * 2;        // 16384
    constexpr int ST_OFF  = XP_OFF + 2 * XPBUF; // 131072
    constexpr int BNP     = BN + 4;

    extern __shared__ __align__(128) char smem[];
    const uint32_t sb = smem_u32(smem);
    float* st = reinterpret_cast<float*>(smem + ST_OFF);

    const int tid = threadIdx.x;
    const int wid = tid >> 5;
    const int lid = tid & 31;
    const int wm  = wid / WGN;
    const int wn  = wid % WGN;
    const int bn0 = blockIdx.x * BN;
    const int bm0 = blockIdx.y * BM;
    const int grp = blockIdx.y;
    const int j0  = bn0 >> 2;

    float c_reg[8];
    #pragma unroll
    for (int k = 0; k < 8; ++k) {
        int idx = tid + 256 * k;
        int r = idx >> 5, jj = idx & 31;
        c_reg[k] = c0[(bm0 + r) * HID + j0 + jj];
    }

    auto loadA = [&](const __half* Ap, int c, int s) {
        const uint32_t ab = sb + s * STG;
        const int k0 = c * BKR;
        #pragma unroll
        for (int it = 0; it < 2; ++it) {   // 64 rows x 8 chunks = 512
            int u = tid + it * 256;
            int r = u >> 3, cc = u & 7;
            CP_ASYNC16(ab + swz64(r, cc),
                       Ap + (size_t)(bm0 + r) * KA + k0 + cc * 8);
        }
    };
    auto loadB = [&](int c, int s) {
        const uint32_t bb = sb + s * STG + A_BYTES;
        const int k0 = c * BKR;
        #pragma unroll
        for (int it = 0; it < 4; ++it) {   // 128 rows x 8 chunks = 1024
            int u = tid + it * 256;
            int r = u >> 3, cc = u & 7;
            CP_ASYNC16(bb + swz64(r, cc),
                       Whhp + (size_t)(bn0 + r) * KA + k0 + cc * 8);
        }
    };
    auto loadXp = [&](int t, int buf) {
        const __half* xsrc = Xp16 + ((size_t)t * BATCH + bm0) * G4 + bn0;
        #pragma unroll
        for (int k = 0; k < 4; ++k) {
            int idx = tid + 256 * k;
            int r = idx >> 4, q = idx & 15;
            CP_ASYNC16(sb + XP_OFF + (uint32_t)buf * XPBUF + (uint32_t)idx * 16,
                       xsrc + (size_t)r * G4 + q * 8);
        }
    };

    unsigned bar_base = 0;
    if (tid == 0) bar_base = ld_acq(&g_bar_gen[grp]);

    // pre-loop "pre-barrier" block for t=0
    loadB(0, 0); CP_COMMIT();
    loadB(1, 1); CP_COMMIT();
    loadB(2, 2); loadXp(0, 0); CP_COMMIT();

    for (int t = 0; t < SEQ; ++t) {
        const __half* Ap = (t == 0) ? h016 : hs16 + (size_t)(t - 1) * BH;
        const __half* xp_s = reinterpret_cast<const __half*>(
            smem + XP_OFF + (t & 1) * XPBUF);

        // post-barrier A loads (depend on h_t)
        loadA(Ap, 0, 0); CP_COMMIT();
        loadA(Ap, 1, 1); CP_COMMIT();
        loadA(Ap, 2, 2); CP_COMMIT();

        float acc[MA][NA][4];
        #pragma unroll
        for (int i = 0; i < MA; ++i)
            #pragma unroll
            for (int j = 0; j < NA; ++j)
                #pragma unroll
                for (int q = 0; q < 4; ++q) acc[i][j][q] = 0.f;

        for (int c = 0; c < NC; ++c) {
            if (c <= NC - 3)      { CP_WAIT2(); }
            else if (c == NC - 2) { CP_WAIT1(); }
            else                  { CP_WAIT0(); }
            __syncthreads();
            if (c + 3 < NC) {
                loadA(Ap, c + 3, (c + 3) & 3);
                loadB(c + 3, (c + 3) & 3);
                CP_COMMIT();
            }

            const uint32_t ab = sb + (c & 3) * STG;
            const uint32_t bb = ab + A_BYTES;
            #pragma unroll
            for (int ks = 0; ks < 4; ++ks) {
                uint32_t afr[MA][4];
                #pragma unroll
                for (int ma = 0; ma < MA; ++ma) {
                    int row = wm * WM + ma * 16 + (lid & 15);
                    int cc  = 2 * ks + (lid >> 4);
                    LDMX4(afr[ma][0], afr[ma][1], afr[ma][2], afr[ma][3],
                          ab + swz64(row, cc));
                }
                uint32_t bfr[NA][2];
                #pragma unroll
                for (int np = 0; np < NA / 2; ++np) {
                    int row = wn * WN + np * 16 + (lid & 15);
                    int cc  = 2 * ks + (lid >> 4);
                    uint32_t r0, r1, r2, r3;
                    LDMX4(r0, r1, r2, r3, bb + swz64(row, cc));
                    bfr[2 * np + 0][0] = r0; bfr[2 * np + 1][0] = r1;
                    bfr[2 * np + 0][1] = r2; bfr[2 * np + 1][1] = r3;
                }
                #pragma unroll
                for (int ma = 0; ma < MA; ++ma)
                    #pragma unroll
                    for (int na = 0; na < NA; ++na)
                        MMA16816(acc[ma][na], afr[ma], bfr[na]);
            }
        }

        const int g  = lid >> 2;
        const int tg = lid & 3;
        #pragma unroll
        for (int ma = 0; ma < MA; ++ma) {
            #pragma unroll
            for (int na = 0; na < NA; ++na) {
                const int col = wn * WN + na * 8 + tg * 2;
                const int r0  = wm * WM + ma * 16 + g;
                const int r1  = r0 + 8;
                st[r0 * BNP + col]     = acc[ma][na][0];
                st[r0 * BNP + col + 1] = acc[ma][na][1];
                st[r1 * BNP + col]     = acc[ma][na][2];
                st[r1 * BNP + col + 1] = acc[ma][na][3];
            }
        }
        __syncthreads();

        __half* hsrow = hs16 + (size_t)t * BH;
        #pragma unroll
        for (int k = 0; k < 8; ++k) {
            int idx = tid + 256 * k;
            int r = idx >> 5, jj = idx & 31;
            float4 gq = *reinterpret_cast<const float4*>(st + r * BNP + 4 * jj);
            uint2 xr = *reinterpret_cast<const uint2*>(
                reinterpret_cast<const char*>(xp_s) + (r * BN + 4 * jj) * 2);
            float2 x01 = __half22float2(*reinterpret_cast<const __half2*>(&xr.x));
            float2 x23 = __half22float2(*reinterpret_cast<const __half2*>(&xr.y));
            float gi = sigmf(gq.x + x01.x);
            float gf = sigmf(gq.y + x01.y);
            float gg = tanhf(gq.z + x23.x);
            float go = sigmf(gq.w + x23.y);
            float cv = gf * c_reg[k] + gi * gg;
            c_reg[k] = cv;
            float h = go * tanhf(cv);
            int b = bm0 + r;
            hsrow[b * HID + j0 + jj] = __float2half(h);
        }

        // pre-barrier prefetch for step t+1 (no h dependence)
        if (t + 1 < SEQ) {
            loadB(0, 0); CP_COMMIT();
            loadB(1, 1); CP_COMMIT();
            loadB(2, 2); loadXp(t + 1, (t + 1) & 1); CP_COMMIT();
        }

        // per-row-group barrier (32 CTAs sharing bm)
        __syncthreads();
        if (tid == 0) {
            __threadfence();
            unsigned a = atomicAdd(&g_bar_cnt[grp], 1);
            if (a == 31u) {
                atomicExch(&g_bar_cnt[grp], 0);
                __threadfence();
                atomicAdd(&g_bar_gen[grp], 1);
            } else {
                unsigned target = bar_base + (unsigned)t + 1u;
                while ((int)(ld_acq(&g_bar_gen[grp]) - target) < 0) { }
            }
        }
        __syncthreads();
    }
}

// ---------------- conversion / small kernels --------------------------------
// vectorized fp32 -> fp16: 8 elems/thread, 16B store
__global__ void conv_act8(const float* __restrict__ W, __half* __restrict__ Wp, int total8)
{
    int i = blockIdx.x * blockDim.x + threadIdx.x;
    if (i >= total8) return;
    float4 a = reinterpret_cast<const float4*>(W)[2 * i];
    float4 b = reinterpret_cast<const float4*>(W)[2 * i + 1];
    __half2 h0 = __floats2half2_rn(a.x, a.y);
    __half2 h1 = __floats2half2_rn(a.z, a.w);
    __half2 h2 = __floats2half2_rn(b.x, b.y);
    __half2 h3 = __floats2half2_rn(b.z, b.w);
    uint4 o;
    o.x = *reinterpret_cast<uint32_t*>(&h0);
    o.y = *reinterpret_cast<uint32_t*>(&h1);
    o.z = *reinterpret_cast<uint32_t*>(&h2);
    o.w = *reinterpret_cast<uint32_t*>(&h3);
    reinterpret_cast<uint4*>(Wp)[i] = o;
}

// vectorized gate-interleaved permutation: orig row q*1024+j -> j*4+q, 8/thread
__global__ void conv_act_perm8(const float* __restrict__ W, __half* __restrict__ Wp, int total8)
{
    int i = blockIdx.x * blockDim.x + threadIdx.x;
    if (i >= total8) return;
    int e = i * 8;
    int r = e >> 10, k = e & 1023;        // k aligned to 8 (8 | 1024)
    int q = r >> 10, j = r & 1023;
    float4 a = reinterpret_cast<const float4*>(W)[2 * i];
    float4 b = reinterpret_cast<const float4*>(W)[2 * i + 1];
    __half2 h0 = __floats2half2_rn(a.x, a.y);
    __half2 h1 = __floats2half2_rn(a.z, a.w);
    __half2 h2 = __floats2half2_rn(b.x, b.y);
    __half2 h3 = __floats2half2_rn(b.z, b.w);
    uint4 o;
    o.x = *reinterpret_cast<uint32_t*>(&h0);
    o.y = *reinterpret_cast<uint32_t*>(&h1);
    o.z = *reinterpret_cast<uint32_t*>(&h2);
    o.w = *reinterpret_cast<uint32_t*>(&h3);
    *reinterpret_cast<uint4*>(Wp + (size_t)(j * 4 + q) * KA + k) = o;
}

__global__ void init_misc()
{
    if (threadIdx.x < 4 && blockIdx.x == 0) {
        g_bar_cnt[threadIdx.x] = 0;
        g_bar_gen[threadIdx.x] = 0;
    }
}

__global__ void bias_combine_perm(const float* __restrict__ b_ih, const float* __restrict__ b_hh)
{
    int i = blockIdx.x * blockDim.x + threadIdx.x;
    if (i >= G4) return;
    int q = i >> 10, j = i & 1023;
    g_bias[j * 4 + q] = b_ih[i] + b_hh[i];
}

// softmax + 2-term fp16 split emit: g_A2[x][0:128]=hi, [128:256]=lo
__global__ void softmax128(const float* __restrict__ W)
{
    int row = blockIdx.x;
    int t = threadIdx.x;
    int lane = t & 31, warp = t >> 5;
    __shared__ float red[4];
    float v = W[row * SEQ + t];

    float m = v;
    #pragma unroll
    for (int o = 16; o > 0; o >>= 1) m = fmaxf(m, __shfl_xor_sync(0xffffffffu, m, o));
    if (lane == 0) red[warp] = m;
    __syncthreads();
    m = fmaxf(fmaxf(red[0], red[1]), fmaxf(red[2], red[3]));
    __syncthreads();

    float e = expf(v - m);
    float s = e;
    #pragma unroll
    for (int o = 16; o > 0; o >>= 1) s += __shfl_xor_sync(0xffffffffu, s, o);
    if (lane == 0) red[warp] = s;
    __syncthreads();
    s = red[0] + red[1] + red[2] + red[3];
    float a = e / s;
    __half hi = __float2half(a);
    float lo = a - __half2float(hi);
    g_A2[row * 256 + t]       = hi;
    g_A2[row * 256 + 128 + t] = __float2half(lo);
}

// hsT16[n][y] = hs16[y][n]; grid (BH/32, SEQ/32), block (32,8)
__global__ void transpose_hs()
{
    __shared__ __half tile[32][34];
    const int tx = threadIdx.x, ty = threadIdx.y;
    const int n0 = blockIdx.x * 32;
    const int y0 = blockIdx.y * 32;
    #pragma unroll
    for (int yy = ty; yy < 32; yy += 8)
        tile[yy][tx] = g_hs16[(size_t)(y0 + yy) * BH + n0 + tx];
    __syncthreads();
    #pragma unroll
    for (int rr = ty; rr < 32; rr += 8)
        g_hsT[(size_t)(n0 + rr) * SEQ + y0 + tx] = tile[tx][rr];
}

// ---------------- launch ----------------------------------------------------
extern "C" void kernel_launch(void* const* d_in, const int* in_sizes, int n_in,
                              void* d_out, int out_size)
{
    const float* inputs = (const float*)d_in[0];
    const float* h0     = (const float*)d_in[1];
    const float* c0     = (const float*)d_in[2];
    const float* W_ih   = (const float*)d_in[3];
    const float* W_hh   = (const float*)d_in[4];
    const float* b_ih   = (const float*)d_in[5];
    const float* b_hh   = (const float*)d_in[6];
    const float* attnW  = (const float*)d_in[7];
    const float* linW   = (const float*)d_in[8];
    const float* linb   = (const float*)d_in[9];
    float* out = (float*)d_out;

    void* p;
    cudaGetSymbolAddress(&p, g_Xp16);  __half* Xp16  = (__half*)p;
    cudaGetSymbolAddress(&p, g_hs16);  __half* hs16  = (__half*)p;
    cudaGetSymbolAddress(&p, g_bias);  float* biasc = (float*)p;
    cudaGetSymbolAddress(&p, g_Xbf);   __half* Xbf   = (__half*)p;
    cudaGetSymbolAddress(&p, g_Wihp);  __half* Wihp  = (__half*)p;
    cudaGetSymbolAddress(&p, g_Whhp);  __half* Whhp  = (__half*)p;
    cudaGetSymbolAddress(&p, g_linWp); __half* linWp = (__half*)p;
    cudaGetSymbolAddress(&p, g_h0);    __half* h016  = (__half*)p;
    cudaGetSymbolAddress(&p, g_A2);    __half* A2    = (__half*)p;
    cudaGetSymbolAddress(&p, g_hsT);   __half* hsT   = (__half*)p;

    const int SMEM_BIG  = 4 * ((128 + 128) * BK * 2);            // 65536
    const int SMEM_PERS = 4 * 24576 + 2 * 16384 + 34816;         // 165888

    cudaFuncSetAttribute((const void*)gemm_mma<128, 128, 2, 4, 1024, 1024, 1024, 0>,
                         cudaFuncAttributeMaxDynamicSharedMemorySize, SMEM_BIG);
    cudaFuncSetAttribute((const void*)gemm_mma<128, 128, 2, 4, 1024, 1024, 1024, 1>,
                         cudaFuncAttributeMaxDynamicSharedMemorySize, SMEM_BIG);
    cudaFuncSetAttribute((const void*)gemm_mma<128, 128, 2, 4, 256, 128, 256, 1>,
                         cudaFuncAttributeMaxDynamicSharedMemorySize, SMEM_BIG);
    cudaFuncSetAttribute((const void*)lstm_persistent,
                         cudaFuncAttributeMaxDynamicSharedMemorySize, SMEM_PERS);

    conv_act8<<<(SEQ * BATCH * 1024 / 8) / 256, 256>>>(inputs, Xbf, SEQ * BATCH * 1024 / 8); // 0
    conv_act_perm8<<<(G4 * 1024 / 8) / 256, 256>>>(W_ih, Wihp, G4 * 1024 / 8);               // 1
    bias_combine_perm<<<(G4 + 255) / 256, 256>>>(b_ih, b_hh);                                // 2
    conv_act_perm8<<<(G4 * 1024 / 8) / 256, 256>>>(W_hh, Whhp, G4 * 1024 / 8);               // 3 (canary)
    conv_act8<<<(BATCH * 1024 / 8) / 256, 256>>>(h0, h016, BATCH * 1024 / 8);                // 4

    // 5: Xp16 = fp16(X16 @ W_ih16^T + bias')
    gemm_mma<128, 128, 2, 4, 1024, 1024, 1024, 1>
        <<<dim3(G4 / 128, (SEQ * BATCH) / 128), 256, SMEM_BIG>>>(
        Xbf, Wihp, biasc, Xp16, G4, 1);

    init_misc<<<1, 32>>>();                                                          // 6
    softmax128<<<SEQ, SEQ>>>(attnW);                                                 // 7

    // 8: persistent recurrence (per-row-group barriers)
    lstm_persistent<<<dim3(G4 / 128, BATCH / 64), 256, SMEM_PERS>>>(
        Whhp, Xp16, c0, hs16, h016);

    // 9: hs16 -> hsT
    transpose_hs<<<dim3(BH / 32, SEQ / 32), dim3(32, 8)>>>();

    conv_act8<<<(OUTD * 1024 / 8) / 256, 256>>>(linW, linWp, OUTD * 1024 / 8);       // 10

    // 11: att16 = (A2 @ hsT^T) via 2-term fp16 HMMA, fp16 out into Xbf
    gemm_mma<128, 128, 2, 4, 256, 128, 256, 1>
        <<<dim3(BH / 128, 1), 256, SMEM_BIG>>>(
        A2, hsT, nullptr, Xbf, BH, 0);

    // 12: out = att16 @ linW16^T + linb
    gemm_mma<128, 128, 2, 4, 1024, 1024, 1024, 0>
        <<<dim3(OUTD / 128, (SEQ * BATCH) / 128), 256, SMEM_BIG>>>(
        Xbf, linWp, linb, out, OUTD, 1);
}